// round 6
// baseline (speedup 1.0000x reference)
#include <cuda_runtime.h>
#include <cstdint>
#include <cstddef>

// ---------------------------------------------------------------------------
// DecoderTreeLSTM — level-parallel persistent kernel (fp32 baseline)
//
// Tree dependency: parent[i] < i. Nodes grouped by depth level; all nodes in
// a level are independent given previous levels. One persistent kernel with a
// software grid barrier (grid == #SMs, 1 CTA/SM via 180KB dynamic smem) walks
// the levels:
//   stage B: batched GEMV/GEMM  g = x@W_iofux + ph@W_iofuh + b ; proj = x@W_px + b
//   stage CD: gates -> c,h,h_final ; dist = h_final@W_out + b ; argmax -> commit
//             scatter embed[commit] into children's pe slots
// ---------------------------------------------------------------------------

#define NT      256
#define NMAX    1024
#define INDIM   2048
#define EMB     200
#define XDIM    2248          // INDIM + EMB
#define HID     1024
#define GC      5120          // 5*HID gate columns
#define OC      6144          // GC + HID (g then proj)
#define NCLS    151
#define MBn     16            // nodes per chunk (register tile)
#define XSTR    20            // smem stride for staged x (float4-aligned)
#define NBLK    48            // 6144 / 128 column blocks
#define SMEMB   (XDIM * XSTR * 4)   // 179840 bytes dynamic smem

// ----- device scratch (static; no allocations anywhere) --------------------
__device__ float g_h[NMAX * HID];
__device__ float g_c[NMAX * HID];
__device__ float g_pe[NMAX * EMB];
__device__ float g_g[NMAX * OC];
__device__ int   g_commit[NMAX];
__device__ int   g_order[NMAX];
__device__ int   g_lvloff[NMAX + 1];
__device__ int   g_choff[NMAX + 1];
__device__ int   g_chlist[NMAX];
__device__ int   g_nlev;
__device__ volatile unsigned g_gen;
__device__ unsigned g_cnt;

// ----- helpers --------------------------------------------------------------
__device__ __forceinline__ float sigf(float x) {
    return 1.0f / (1.0f + expf(-x));
}

// Sense-reversing grid barrier. Safe because grid <= #SMs and 180KB smem
// forces occupancy 1 -> all CTAs co-resident. Every thread fences its own
// writes before arrival.
__device__ __forceinline__ void grid_sync() {
    __threadfence();
    __syncthreads();
    if (threadIdx.x == 0) {
        unsigned gen = g_gen;
        unsigned a = atomicAdd(&g_cnt, 1u);
        if (a == gridDim.x - 1u) {
            g_cnt = 0u;
            __threadfence();
            g_gen = gen + 1u;
        } else {
            while (g_gen == gen) { __nanosleep(64); }
        }
    }
    __syncthreads();
}

// Rank-1-update GEMV core: each thread owns 4 columns x 16 nodes of fp32
// accumulators; per k: 1 LDG.128 of W row slice + 4 LDS.128 broadcast of x.
__device__ __forceinline__ void pass_accum(
    const float* __restrict__ Wb,   // pre-offset by column
    int stride,                      // row stride in floats
    const float* __restrict__ xs,    // smem staged [k][XSTR]
    int k0, int k1,
    float4 acc[16])
{
#pragma unroll 2
    for (int k = k0; k < k1; ++k) {
        float4 w = *reinterpret_cast<const float4*>(Wb + (size_t)k * stride);
        const float4* xr = reinterpret_cast<const float4*>(xs + k * XSTR);
        float4 x0 = xr[0], x1 = xr[1], x2 = xr[2], x3 = xr[3];
        float xm[16] = { x0.x, x0.y, x0.z, x0.w,  x1.x, x1.y, x1.z, x1.w,
                         x2.x, x2.y, x2.z, x2.w,  x3.x, x3.y, x3.z, x3.w };
#pragma unroll
        for (int m = 0; m < 16; ++m) {
            acc[m].x = fmaf(w.x, xm[m], acc[m].x);
            acc[m].y = fmaf(w.y, xm[m], acc[m].y);
            acc[m].z = fmaf(w.z, xm[m], acc[m].z);
            acc[m].w = fmaf(w.w, xm[m], acc[m].w);
        }
    }
}

// ----- the persistent kernel -------------------------------------------------
__global__ void __launch_bounds__(NT, 1)
tree_lstm_kernel(const float* __restrict__ features,
                 const int*   __restrict__ parent,
                 const int*   __restrict__ bsz_ptr,     // may be null -> B=8
                 const float* __restrict__ W_px,   const float* __restrict__ b_px,
                 const float* __restrict__ W_iofux,const float* __restrict__ b_iofux,
                 const float* __restrict__ W_iofuh,const float* __restrict__ b_iofuh,
                 const float* __restrict__ W_out,  const float* __restrict__ b_out,
                 const float* __restrict__ embed,
                 float* __restrict__ out,
                 int n, long long out_size)
{
    extern __shared__ float smf[];
    const int tid = threadIdx.x;
    const int B = bsz_ptr ? bsz_ptr[0] : 8;

    // ================= PREP (CTA 0) =================
    if (blockIdx.x == 0) {
        int* si  = reinterpret_cast<int*>(smf);
        int* anc = si;
        int* lv  = si + 1024;
        int* cnt = si + 2048;
        int* cur = si + 3072;

        for (int i = tid; i < n; i += NT) {
            int p = parent[i];
            anc[i] = p;
            lv[i]  = (p >= 0) ? 1 : 0;
        }
        __syncthreads();

        // pointer-doubling depth computation: 10 iterations covers depth<=1023
        for (int it = 0; it < 10; ++it) {
            int ra[4], rl[4];
            int q = 0;
            for (int i = tid; i < n; i += NT, ++q) {
                int a = anc[i];
                rl[q] = (a >= 0) ? lv[a]  : 0;
                ra[q] = (a >= 0) ? anc[a] : -1;
            }
            __syncthreads();
            q = 0;
            for (int i = tid; i < n; i += NT, ++q) {
                lv[i]  += rl[q];
                anc[i]  = ra[q];
            }
            __syncthreads();
        }

        // level histogram + max level
        for (int i = tid; i < n; i += NT) cnt[i] = 0;
        if (tid == 0) si[4096] = 0;
        __syncthreads();
        int mx = 0;
        for (int i = tid; i < n; i += NT) {
            atomicAdd(&cnt[lv[i]], 1);
            if (lv[i] > mx) mx = lv[i];
        }
        atomicMax(&si[4096], mx);
        __syncthreads();
        int nlev = si[4096] + 1;

        if (tid == 0) {
            int s0 = 0;
            for (int l = 0; l < nlev; ++l) {
                g_lvloff[l] = s0; cur[l] = s0; s0 += cnt[l];
            }
            g_lvloff[nlev] = s0;
            g_nlev = nlev;
        }
        __syncthreads();
        for (int i = tid; i < n; i += NT) {
            int pos = atomicAdd(&cur[lv[i]], 1);
            g_order[pos] = i;
        }
        __syncthreads();

        // children CSR
        for (int i = tid; i < n; i += NT) cnt[i] = 0;
        __syncthreads();
        for (int i = tid; i < n; i += NT) {
            int p = parent[i];
            if (p >= 0) atomicAdd(&cnt[p], 1);
        }
        __syncthreads();
        if (tid == 0) {
            int s0 = 0;
            for (int i = 0; i < n; ++i) { g_choff[i] = s0; cur[i] = s0; s0 += cnt[i]; }
            g_choff[n] = s0;
        }
        __syncthreads();
        for (int i = tid; i < n; i += NT) {
            int p = parent[i];
            if (p >= 0) {
                int e = atomicAdd(&cur[p], 1);
                g_chlist[e] = i;
            }
        }
        // roots: pe = embed_table[0]
        for (int i = tid; i < n; i += NT) {
            if (parent[i] < 0) {
                for (int d = 0; d < EMB; ++d)
                    g_pe[(size_t)i * EMB + d] = embed[d];
            }
        }
    }
    grid_sync();

    const int nlev = g_nlev;

    // ================= LEVEL LOOP =================
    for (int lev = 0; lev < nlev; ++lev) {
        const int lo = g_lvloff[lev];
        const int hi = g_lvloff[lev + 1];
        const int W  = hi - lo;

        // ---------- stage B: batched GEMVs ----------
        const int chunks = (W + MBn - 1) / MBn;
        const int ntasks = NBLK * chunks;
        for (int task = blockIdx.x; task < ntasks; task += gridDim.x) {
            const int cb    = task % NBLK;
            const int chunk = task / NBLK;
            const int base  = lo + chunk * MBn;
            float* xs = smf;

            // stage x = [features | pe], transposed: xs[k][m]
            for (int idx = tid; idx < MBn * XDIM; idx += NT) {
                int m = idx / XDIM;
                int k = idx - m * XDIM;
                int slot = base + m; if (slot > hi - 1) slot = hi - 1;
                int node = g_order[slot];
                float v = (k < INDIM)
                            ? features[(size_t)node * INDIM + k]
                            : g_pe[(size_t)node * EMB + (k - INDIM)];
                xs[k * XSTR + m] = v;
            }
            __syncthreads();

            const int colt = tid & 31;
            const int kp   = tid >> 5;
            float4 acc[16];
#pragma unroll
            for (int m = 0; m < 16; ++m) acc[m] = make_float4(0.f, 0.f, 0.f, 0.f);

            const float* Wb;
            int stride;
            if (cb < 40) { stride = GC;  Wb = W_iofux + cb * 128 + colt * 4; }
            else         { stride = HID; Wb = W_px + (cb - 40) * 128 + colt * 4; }

            pass_accum(Wb, stride, xs, kp * 281, kp * 281 + 281, acc);   // K=2248 split 8

            if (cb < 40) {
                __syncthreads();
                // restage ph = h[parent] (0 for roots) in same smem
                for (int idx = tid; idx < MBn * HID; idx += NT) {
                    int m = idx / HID;
                    int k = idx - m * HID;
                    int slot = base + m; if (slot > hi - 1) slot = hi - 1;
                    int node = g_order[slot];
                    int par  = parent[node];
                    xs[k * XSTR + m] = (par >= 0) ? g_h[(size_t)par * HID + k] : 0.0f;
                }
                __syncthreads();
                pass_accum(W_iofuh + cb * 128 + colt * 4, GC, xs,
                           kp * 128, kp * 128 + 128, acc);                // K=1024 split 8
            }

            // k-split reduction through smem (overlaps xs region)
            __syncthreads();
            float* red = smf;
#pragma unroll
            for (int m = 0; m < 16; ++m)
                *reinterpret_cast<float4*>(red + kp * 2048 + m * 128 + colt * 4) = acc[m];
            __syncthreads();

            {
                const int cg  = tid & 31;
                const int mb2 = (tid >> 5) * 2;
#pragma unroll
                for (int mm = 0; mm < 2; ++mm) {
                    const int m = mb2 + mm;
                    float4 s = make_float4(0.f, 0.f, 0.f, 0.f);
#pragma unroll
                    for (int p = 0; p < 8; ++p) {
                        float4 v = *reinterpret_cast<const float4*>(
                            red + p * 2048 + m * 128 + cg * 4);
                        s.x += v.x; s.y += v.y; s.z += v.z; s.w += v.w;
                    }
                    int gcol; float4 bb;
                    if (cb < 40) {
                        gcol = cb * 128 + cg * 4;
                        float4 b1 = *reinterpret_cast<const float4*>(b_iofux + gcol);
                        float4 b2 = *reinterpret_cast<const float4*>(b_iofuh + gcol);
                        bb = make_float4(b1.x + b2.x, b1.y + b2.y,
                                         b1.z + b2.z, b1.w + b2.w);
                    } else {
                        int pcol = (cb - 40) * 128 + cg * 4;
                        bb   = *reinterpret_cast<const float4*>(b_px + pcol);
                        gcol = GC + pcol;
                    }
                    s.x += bb.x; s.y += bb.y; s.z += bb.z; s.w += bb.w;
                    int slot = base + m; if (slot > hi - 1) slot = hi - 1;
                    int node = g_order[slot];
                    *reinterpret_cast<float4*>(g_g + (size_t)node * OC + gcol) = s;
                }
            }
            __syncthreads();
        }
        grid_sync();

        // ---------- stage CD: gates + output head, one CTA per node ----------
        for (int s = blockIdx.x; s < W; s += gridDim.x) {
            const int node = g_order[lo + s];
            const int par  = parent[node];
            const float* grow = g_g + (size_t)node * OC;
            float* hb = smf;            // h_final, 1024 floats
            float* db = smf + HID;      // dist, 151 floats

            const int j = tid * 4;      // 256*4 == 1024 exactly
            float4 ig4 = *reinterpret_cast<const float4*>(grow + j);
            float4 og4 = *reinterpret_cast<const float4*>(grow + HID + j);
            float4 fg4 = *reinterpret_cast<const float4*>(grow + 2 * HID + j);
            float4 ug4 = *reinterpret_cast<const float4*>(grow + 3 * HID + j);
            float4 rg4 = *reinterpret_cast<const float4*>(grow + 4 * HID + j);
            float4 pj4 = *reinterpret_cast<const float4*>(grow + 5 * HID + j);
            float4 pc4 = make_float4(0.f, 0.f, 0.f, 0.f);
            if (par >= 0)
                pc4 = *reinterpret_cast<const float4*>(g_c + (size_t)par * HID + j);

            float4 c4, hf4;
            {
                float iS, oS, fS, rS, cv, hv;
#define ELT(CC, HH, IG, OG, FG, UG, RG, PJ, PC)            \
                iS = sigf(IG); oS = sigf(OG); fS = sigf(FG); rS = sigf(RG); \
                cv = iS * tanhf(UG) + fS * (PC);           \
                hv = oS * tanhf(cv);                       \
                CC = cv; HH = rS * hv + (1.0f - rS) * (PJ);
                ELT(c4.x, hf4.x, ig4.x, og4.x, fg4.x, ug4.x, rg4.x, pj4.x, pc4.x)
                ELT(c4.y, hf4.y, ig4.y, og4.y, fg4.y, ug4.y, rg4.y, pj4.y, pc4.y)
                ELT(c4.z, hf4.z, ig4.z, og4.z, fg4.z, ug4.z, rg4.z, pj4.z, pc4.z)
                ELT(c4.w, hf4.w, ig4.w, og4.w, fg4.w, ug4.w, rg4.w, pj4.w, pc4.w)
#undef ELT
            }
            *reinterpret_cast<float4*>(g_c + (size_t)node * HID + j) = c4;
            *reinterpret_cast<float4*>(g_h + (size_t)node * HID + j) = hf4;
            *reinterpret_cast<float4*>(hb + j) = hf4;
            __syncthreads();

            // dist = h_final @ W_out + b_out
            if (tid < NCLS) {
                float a = b_out[tid];
                const float* wc = W_out + tid;
#pragma unroll 8
                for (int k = 0; k < HID; ++k)
                    a = fmaf(hb[k], wc[(size_t)k * NCLS], a);
                db[tid] = a;
                if (node >= B) {
                    size_t off = (size_t)(node - B) * NCLS + tid;
                    if (off < (size_t)out_size) out[off] = a;
                }
            }
            __syncthreads();

            // argmax over dist[1:], first-max semantics (matches jnp.argmax)
            if (tid == 0) {
                float best = db[1]; int bi = 1;
                for (int q = 2; q < NCLS; ++q) {
                    float v = db[q];
                    if (v > best) { best = v; bi = q; }
                }
                g_commit[node] = bi;
                reinterpret_cast<int*>(smf)[1280] = bi;
            }
            __syncthreads();

            // scatter embed[commit] into children's pe slots
            const int cm = reinterpret_cast<int*>(smf)[1280];
            const int cs = g_choff[node];
            const int ce = g_choff[node + 1];
            const int tot = (ce - cs) * EMB;
            const float* erow = embed + (size_t)cm * EMB;
            for (int e = tid; e < tot; e += NT) {
                int ch = g_chlist[cs + e / EMB];
                int d  = e - (e / EMB) * EMB;
                g_pe[(size_t)ch * EMB + d] = erow[d];
            }
            __syncthreads();
        }
        grid_sync();
    }

    // ================= commitments tail =================
    const int NBo = n - B;
    for (int jj = blockIdx.x * NT + tid; jj < n; jj += gridDim.x * NT) {
        size_t off = (size_t)NBo * NCLS + jj;
        if (off < (size_t)out_size) {
            float v = (jj < NBo) ? (float)g_commit[B + jj] : 0.0f;
            out[off] = v;
        }
    }
}

// ----- host launcher ----------------------------------------------------------
extern "C" void kernel_launch(void* const* d_in, const int* in_sizes, int n_in,
                              void* d_out, int out_size)
{
    const float* features = (const float*)d_in[0];
    const int*   parent   = (const int*)  d_in[1];

    const int* bptr = nullptr;
    int base = 2;
    if (n_in >= 12) { bptr = (const int*)d_in[2]; base = 3; }

    const float* W_px    = (const float*)d_in[base + 0];
    const float* b_px    = (const float*)d_in[base + 1];
    const float* W_iofux = (const float*)d_in[base + 2];
    const float* b_iofux = (const float*)d_in[base + 3];
    const float* W_iofuh = (const float*)d_in[base + 4];
    const float* b_iofuh = (const float*)d_in[base + 5];
    const float* W_out   = (const float*)d_in[base + 6];
    const float* b_out   = (const float*)d_in[base + 7];
    const float* embed   = (const float*)d_in[base + 8];

    int n = in_sizes[1];
    if (n > NMAX) n = NMAX;

    int dev = 0, sms = 0;
    cudaGetDevice(&dev);
    cudaDeviceGetAttribute(&sms, cudaDevAttrMultiProcessorCount, dev);
    if (sms <= 0) sms = 148;

    cudaFuncSetAttribute(tree_lstm_kernel,
                         cudaFuncAttributeMaxDynamicSharedMemorySize, SMEMB);

    tree_lstm_kernel<<<sms, NT, SMEMB>>>(
        features, parent, bptr,
        W_px, b_px, W_iofux, b_iofux, W_iofuh, b_iofuh,
        W_out, b_out, embed,
        (float*)d_out, n, (long long)out_size);
}

// round 7
// speedup vs baseline: 1.8491x; 1.8491x over previous
#include <cuda_runtime.h>
#include <cstdint>
#include <cstddef>

// ---------------------------------------------------------------------------
// DecoderTreeLSTM — level-parallel persistent kernel, round 6
//   * NT=512 (16 warps/SM) for latency hiding
//   * packed fma.rn.f32x2 inner loop (2x fp32 rate on Blackwell)
//   * node-paired accumulators (x-pairs free from LDS, only 4 w-dups per k)
//   * XSTR=18 staging (2-way store conflicts, LDS.64 broadcast reads)
// ---------------------------------------------------------------------------

#define NT      512
#define NMAX    1024
#define INDIM   2048
#define EMB     200
#define XDIM    2248          // INDIM + EMB
#define HID     1024
#define GC      5120          // 5*HID gate columns
#define OC      6144          // GC + HID (g then proj)
#define NCLS    151
#define MBn     16            // nodes per chunk (register tile)
#define XSTR    18            // smem stride for staged x (float2-aligned, 2-way conflicts)
#define NBLK    48            // 6144 / 128 column blocks
#define KSPLIT  16            // one warp per k-slice
#define SMEMB   (XDIM * XSTR * 4)   // 161856 bytes dynamic smem

// ----- device scratch (static; no allocations anywhere) --------------------
__device__ float g_h[NMAX * HID];
__device__ float g_c[NMAX * HID];
__device__ float g_pe[NMAX * EMB];
__device__ float g_g[NMAX * OC];
__device__ int   g_commit[NMAX];
__device__ int   g_order[NMAX];
__device__ int   g_lvloff[NMAX + 1];
__device__ int   g_choff[NMAX + 1];
__device__ int   g_chlist[NMAX];
__device__ int   g_nlev;
__device__ volatile unsigned g_gen;
__device__ unsigned g_cnt;

// ----- helpers --------------------------------------------------------------
__device__ __forceinline__ float sigf(float x) {
    return 1.0f / (1.0f + expf(-x));
}

// packed dual-fp32 fma: d = a*b + c on both lanes (exact fp32 numerics)
__device__ __forceinline__ float2 ffma2(float2 a, float2 b, float2 c) {
    unsigned long long ua = reinterpret_cast<unsigned long long&>(a);
    unsigned long long ub = reinterpret_cast<unsigned long long&>(b);
    unsigned long long uc = reinterpret_cast<unsigned long long&>(c);
    unsigned long long ud;
    asm("fma.rn.f32x2 %0, %1, %2, %3;" : "=l"(ud) : "l"(ua), "l"(ub), "l"(uc));
    return reinterpret_cast<float2&>(ud);
}

// Sense-reversing grid barrier. Safe: grid == #SMs, big smem forces 1 CTA/SM.
__device__ __forceinline__ void grid_sync() {
    __threadfence();
    __syncthreads();
    if (threadIdx.x == 0) {
        unsigned gen = g_gen;
        unsigned a = atomicAdd(&g_cnt, 1u);
        if (a == gridDim.x - 1u) {
            g_cnt = 0u;
            __threadfence();
            g_gen = gen + 1u;
        } else {
            while (g_gen == gen) { __nanosleep(64); }
        }
    }
    __syncthreads();
}

// FFMA2 rank-1 update core.
// Each thread: 4 cols (colt*4) x 16 nodes as 8 node-pairs -> 32 f32x2 accs.
// Per k: 1 LDG.128 (W), 8 LDS.64 broadcast (x pairs), 4 dup-packs, 32 FFMA2.
__device__ __forceinline__ void pass_accum2(
    const float* __restrict__ Wb,   // pre-offset by column
    int stride,                      // W row stride in floats
    const float* __restrict__ xs,    // smem staged [k][XSTR], nodes contiguous
    int k0, int k1,
    float2 acc[8][4])
{
    const float* wp = Wb + (size_t)k0 * stride;
    const float* xp0 = xs + (size_t)k0 * XSTR;
#pragma unroll 2
    for (int k = k0; k < k1; ++k) {
        float4 w = *reinterpret_cast<const float4*>(wp);
        wp += stride;
        float2 wd0 = make_float2(w.x, w.x);
        float2 wd1 = make_float2(w.y, w.y);
        float2 wd2 = make_float2(w.z, w.z);
        float2 wd3 = make_float2(w.w, w.w);
        const float2* xr = reinterpret_cast<const float2*>(xp0);
        xp0 += XSTR;
        float2 xp[8];
#pragma unroll
        for (int p = 0; p < 8; ++p) xp[p] = xr[p];
#pragma unroll
        for (int p = 0; p < 8; ++p) {
            acc[p][0] = ffma2(xp[p], wd0, acc[p][0]);
            acc[p][1] = ffma2(xp[p], wd1, acc[p][1]);
            acc[p][2] = ffma2(xp[p], wd2, acc[p][2]);
            acc[p][3] = ffma2(xp[p], wd3, acc[p][3]);
        }
    }
}

// ----- the persistent kernel -------------------------------------------------
__global__ void __launch_bounds__(NT, 1)
tree_lstm_kernel(const float* __restrict__ features,
                 const int*   __restrict__ parent,
                 const int*   __restrict__ bsz_ptr,
                 const float* __restrict__ W_px,   const float* __restrict__ b_px,
                 const float* __restrict__ W_iofux,const float* __restrict__ b_iofux,
                 const float* __restrict__ W_iofuh,const float* __restrict__ b_iofuh,
                 const float* __restrict__ W_out,  const float* __restrict__ b_out,
                 const float* __restrict__ embed,
                 float* __restrict__ out,
                 int n, long long out_size)
{
    extern __shared__ float smf[];
    const int tid = threadIdx.x;
    const int B = bsz_ptr ? bsz_ptr[0] : 8;

    // ================= PREP (CTA 0) =================
    if (blockIdx.x == 0) {
        int* si  = reinterpret_cast<int*>(smf);
        int* anc = si;
        int* lv  = si + 1024;
        int* cnt = si + 2048;
        int* cur = si + 3072;

        for (int i = tid; i < n; i += NT) {
            int p = parent[i];
            anc[i] = p;
            lv[i]  = (p >= 0) ? 1 : 0;
        }
        __syncthreads();

        for (int it = 0; it < 10; ++it) {     // pointer-doubling depth
            int ra[2], rl[2];
            int q = 0;
            for (int i = tid; i < n; i += NT, ++q) {
                int a = anc[i];
                rl[q] = (a >= 0) ? lv[a]  : 0;
                ra[q] = (a >= 0) ? anc[a] : -1;
            }
            __syncthreads();
            q = 0;
            for (int i = tid; i < n; i += NT, ++q) {
                lv[i]  += rl[q];
                anc[i]  = ra[q];
            }
            __syncthreads();
        }

        for (int i = tid; i < n; i += NT) cnt[i] = 0;
        if (tid == 0) si[4096] = 0;
        __syncthreads();
        int mx = 0;
        for (int i = tid; i < n; i += NT) {
            atomicAdd(&cnt[lv[i]], 1);
            if (lv[i] > mx) mx = lv[i];
        }
        atomicMax(&si[4096], mx);
        __syncthreads();
        int nlev = si[4096] + 1;

        if (tid == 0) {
            int s0 = 0;
            for (int l = 0; l < nlev; ++l) { g_lvloff[l] = s0; cur[l] = s0; s0 += cnt[l]; }
            g_lvloff[nlev] = s0;
            g_nlev = nlev;
        }
        __syncthreads();
        for (int i = tid; i < n; i += NT) {
            int pos = atomicAdd(&cur[lv[i]], 1);
            g_order[pos] = i;
        }
        __syncthreads();

        // children CSR
        for (int i = tid; i < n; i += NT) cnt[i] = 0;
        __syncthreads();
        for (int i = tid; i < n; i += NT) {
            int p = parent[i];
            if (p >= 0) atomicAdd(&cnt[p], 1);
        }
        __syncthreads();
        if (tid == 0) {
            int s0 = 0;
            for (int i = 0; i < n; ++i) { g_choff[i] = s0; cur[i] = s0; s0 += cnt[i]; }
            g_choff[n] = s0;
        }
        __syncthreads();
        for (int i = tid; i < n; i += NT) {
            int p = parent[i];
            if (p >= 0) {
                int e = atomicAdd(&cur[p], 1);
                g_chlist[e] = i;
            }
        }
        for (int i = tid; i < n; i += NT) {
            if (parent[i] < 0)
                for (int d = 0; d < EMB; ++d)
                    g_pe[(size_t)i * EMB + d] = embed[d];
        }
    }
    grid_sync();

    const int nlev = g_nlev;

    // ================= LEVEL LOOP =================
    for (int lev = 0; lev < nlev; ++lev) {
        const int lo = g_lvloff[lev];
        const int hi = g_lvloff[lev + 1];
        const int W  = hi - lo;

        // ---------- stage B: batched GEMVs ----------
        const int chunks = (W + MBn - 1) / MBn;
        const int ntasks = NBLK * chunks;
        for (int task = blockIdx.x; task < ntasks; task += gridDim.x) {
            const int cb    = task % NBLK;
            const int chunk = task / NBLK;
            const int base  = lo + chunk * MBn;
            float* xs = smf;

            // stage x = [features | pe], transposed: xs[k*XSTR + m]
            for (int idx = tid; idx < MBn * XDIM; idx += NT) {
                int m = idx / XDIM;
                int k = idx - m * XDIM;
                int slot = base + m; if (slot > hi - 1) slot = hi - 1;
                int node = g_order[slot];
                float v = (k < INDIM)
                            ? features[(size_t)node * INDIM + k]
                            : g_pe[(size_t)node * EMB + (k - INDIM)];
                xs[k * XSTR + m] = v;
            }
            __syncthreads();

            const int colt = tid & 31;
            const int kp   = tid >> 5;            // warp id == k-slice
            float2 acc[8][4];
#pragma unroll
            for (int p = 0; p < 8; ++p)
#pragma unroll
                for (int c = 0; c < 4; ++c) acc[p][c] = make_float2(0.f, 0.f);

            const float* Wb;
            int stride;
            if (cb < 40) { stride = GC;  Wb = W_iofux + cb * 128 + colt * 4; }
            else         { stride = HID; Wb = W_px + (cb - 40) * 128 + colt * 4; }

            {   // x pass: K = 2248 split over 16 warps
                int k0 = (kp * XDIM) / KSPLIT;
                int k1 = ((kp + 1) * XDIM) / KSPLIT;
                pass_accum2(Wb, stride, xs, k0, k1, acc);
            }

            if (cb < 40) {
                __syncthreads();
                // restage ph = h[parent] (0 for roots) in same smem
                for (int idx = tid; idx < MBn * HID; idx += NT) {
                    int m = idx / HID;
                    int k = idx - m * HID;
                    int slot = base + m; if (slot > hi - 1) slot = hi - 1;
                    int node = g_order[slot];
                    int par  = parent[node];
                    xs[k * XSTR + m] = (par >= 0) ? g_h[(size_t)par * HID + k] : 0.0f;
                }
                __syncthreads();
                int k0 = kp * (HID / KSPLIT);
                pass_accum2(W_iofuh + cb * 128 + colt * 4, GC, xs,
                            k0, k0 + HID / KSPLIT, acc);
            }

            // k-split reduction through smem (overlaps xs region)
            __syncthreads();
            float* red = smf;
#pragma unroll
            for (int p = 0; p < 8; ++p) {
                float4 lo4 = make_float4(acc[p][0].x, acc[p][1].x, acc[p][2].x, acc[p][3].x);
                float4 hi4 = make_float4(acc[p][0].y, acc[p][1].y, acc[p][2].y, acc[p][3].y);
                *reinterpret_cast<float4*>(red + kp * 2048 + (2 * p)     * 128 + colt * 4) = lo4;
                *reinterpret_cast<float4*>(red + kp * 2048 + (2 * p + 1) * 128 + colt * 4) = hi4;
            }
            __syncthreads();

            {   // each thread reduces exactly one float4 output
                const int m  = tid >> 5;
                const int cg = tid & 31;
                float4 s = make_float4(0.f, 0.f, 0.f, 0.f);
#pragma unroll
                for (int p = 0; p < KSPLIT; ++p) {
                    float4 v = *reinterpret_cast<const float4*>(
                        red + p * 2048 + m * 128 + cg * 4);
                    s.x += v.x; s.y += v.y; s.z += v.z; s.w += v.w;
                }
                int gcol; float4 bb;
                if (cb < 40) {
                    gcol = cb * 128 + cg * 4;
                    float4 b1 = *reinterpret_cast<const float4*>(b_iofux + gcol);
                    float4 b2 = *reinterpret_cast<const float4*>(b_iofuh + gcol);
                    bb = make_float4(b1.x + b2.x, b1.y + b2.y, b1.z + b2.z, b1.w + b2.w);
                } else {
                    int pcol = (cb - 40) * 128 + cg * 4;
                    bb   = *reinterpret_cast<const float4*>(b_px + pcol);
                    gcol = GC + pcol;
                }
                s.x += bb.x; s.y += bb.y; s.z += bb.z; s.w += bb.w;
                int slot = base + m; if (slot > hi - 1) slot = hi - 1;
                int node = g_order[slot];
                *reinterpret_cast<float4*>(g_g + (size_t)node * OC + gcol) = s;
            }
            __syncthreads();   // protect red before next task's staging
        }
        grid_sync();

        // ---------- stage CD: gates + output head, one CTA per node ----------
        for (int s = blockIdx.x; s < W; s += gridDim.x) {
            const int node = g_order[lo + s];
            const int par  = parent[node];
            const float* grow = g_g + (size_t)node * OC;
            float* hb   = smf;              // h_final, 1024 floats
            float* part = smf + HID;        // 512 partials for W_out GEMV
            float* db   = smf + HID + 512;  // dist, 151 floats
            int*   cms  = reinterpret_cast<int*>(smf) + HID + 512 + 256;

            const int j = tid * 2;          // 512*2 == 1024
            float2 ig2 = *reinterpret_cast<const float2*>(grow + j);
            float2 og2 = *reinterpret_cast<const float2*>(grow + HID + j);
            float2 fg2 = *reinterpret_cast<const float2*>(grow + 2 * HID + j);
            float2 ug2 = *reinterpret_cast<const float2*>(grow + 3 * HID + j);
            float2 rg2 = *reinterpret_cast<const float2*>(grow + 4 * HID + j);
            float2 pj2 = *reinterpret_cast<const float2*>(grow + 5 * HID + j);
            float2 pc2 = make_float2(0.f, 0.f);
            if (par >= 0)
                pc2 = *reinterpret_cast<const float2*>(g_c + (size_t)par * HID + j);

            float2 c2, hf2;
            {
                float iS, oS, fS, rS, cv, hv;
#define ELT(CC, HH, IG, OG, FG, UG, RG, PJ, PC)            \
                iS = sigf(IG); oS = sigf(OG); fS = sigf(FG); rS = sigf(RG); \
                cv = iS * tanhf(UG) + fS * (PC);           \
                hv = oS * tanhf(cv);                       \
                CC = cv; HH = rS * hv + (1.0f - rS) * (PJ);
                ELT(c2.x, hf2.x, ig2.x, og2.x, fg2.x, ug2.x, rg2.x, pj2.x, pc2.x)
                ELT(c2.y, hf2.y, ig2.y, og2.y, fg2.y, ug2.y, rg2.y, pj2.y, pc2.y)
#undef ELT
            }
            *reinterpret_cast<float2*>(g_c + (size_t)node * HID + j) = c2;
            *reinterpret_cast<float2*>(g_h + (size_t)node * HID + j) = hf2;
            *reinterpret_cast<float2*>(hb + j) = hf2;
            __syncthreads();

            // dist = h_final @ W_out + b_out ; 2-way k-split
            {
                const int c   = tid & 255;
                const int seg = tid >> 8;
                if (c < NCLS) {
                    const float* wc = W_out + c;
                    const int k0 = seg * 512;
                    float a = (seg == 0) ? b_out[c] : 0.0f;
#pragma unroll 8
                    for (int k = k0; k < k0 + 512; ++k)
                        a = fmaf(hb[k], wc[(size_t)k * NCLS], a);
                    part[seg * 256 + c] = a;
                }
            }
            __syncthreads();
            if (tid < NCLS) {
                float a = part[tid] + part[256 + tid];
                db[tid] = a;
                if (node >= B) {
                    size_t off = (size_t)(node - B) * NCLS + tid;
                    if (off < (size_t)out_size) out[off] = a;
                }
            }
            __syncthreads();

            // warp-parallel argmax over dist[1:], first-max semantics
            if (tid < 32) {
                float best = -3.4e38f; int bi = NCLS;
                for (int q = 1 + tid; q < NCLS; q += 32) {
                    float v = db[q];
                    if (v > best) { best = v; bi = q; }
                }
#pragma unroll
                for (int off = 16; off > 0; off >>= 1) {
                    float ov = __shfl_down_sync(0xffffffffu, best, off);
                    int   oi = __shfl_down_sync(0xffffffffu, bi, off);
                    if (ov > best || (ov == best && oi < bi)) { best = ov; bi = oi; }
                }
                if (tid == 0) { g_commit[node] = bi; cms[0] = bi; }
            }
            __syncthreads();

            // scatter embed[commit] into children's pe slots
            const int cm = cms[0];
            const int cs = g_choff[node];
            const int ce = g_choff[node + 1];
            const int tot = (ce - cs) * EMB;
            const float* erow = embed + (size_t)cm * EMB;
            for (int e = tid; e < tot; e += NT) {
                int q = e / EMB;
                int d = e - q * EMB;
                int ch = g_chlist[cs + q];
                g_pe[(size_t)ch * EMB + d] = erow[d];
            }
            __syncthreads();
        }
        grid_sync();
    }

    // ================= commitments tail =================
    const int NBo = n - B;
    for (int jj = blockIdx.x * NT + tid; jj < n; jj += gridDim.x * NT) {
        size_t off = (size_t)NBo * NCLS + jj;
        if (off < (size_t)out_size) {
            float v = (jj < NBo) ? (float)g_commit[B + jj] : 0.0f;
            out[off] = v;
        }
    }
}

// ----- host launcher ----------------------------------------------------------
extern "C" void kernel_launch(void* const* d_in, const int* in_sizes, int n_in,
                              void* d_out, int out_size)
{
    const float* features = (const float*)d_in[0];
    const int*   parent   = (const int*)  d_in[1];

    const int* bptr = nullptr;
    int base = 2;
    if (n_in >= 12) { bptr = (const int*)d_in[2]; base = 3; }

    const float* W_px    = (const float*)d_in[base + 0];
    const float* b_px    = (const float*)d_in[base + 1];
    const float* W_iofux = (const float*)d_in[base + 2];
    const float* b_iofux = (const float*)d_in[base + 3];
    const float* W_iofuh = (const float*)d_in[base + 4];
    const float* b_iofuh = (const float*)d_in[base + 5];
    const float* W_out   = (const float*)d_in[base + 6];
    const float* b_out   = (const float*)d_in[base + 7];
    const float* embed   = (const float*)d_in[base + 8];

    int n = in_sizes[1];
    if (n > NMAX) n = NMAX;

    int dev = 0, sms = 0;
    cudaGetDevice(&dev);
    cudaDeviceGetAttribute(&sms, cudaDevAttrMultiProcessorCount, dev);
    if (sms <= 0) sms = 148;

    cudaFuncSetAttribute(tree_lstm_kernel,
                         cudaFuncAttributeMaxDynamicSharedMemorySize, SMEMB);

    tree_lstm_kernel<<<sms, NT, SMEMB>>>(
        features, parent, bptr,
        W_px, b_px, W_iofux, b_iofux, W_iofuh, b_iofuh,
        W_out, b_out, embed,
        (float*)d_out, n, (long long)out_size);
}

// round 8
// speedup vs baseline: 1.8531x; 1.0021x over previous
#include <cuda_runtime.h>
#include <cstdint>
#include <cstddef>

// ---------------------------------------------------------------------------
// DecoderTreeLSTM — level-parallel persistent kernel, round 7
//   * software-pipelined inner loop: W prefetch depth 4 (MLP=4 per warp)
//   * XSTR=20: x read as 4x LDS.128 broadcast (was 8x LDS.64)
//   * div-free staging loops; 4-accumulator W_out GEMV in CD stage
// ---------------------------------------------------------------------------

#define NT      512
#define NMAX    1024
#define INDIM   2048
#define EMB     200
#define XDIM    2248          // INDIM + EMB
#define HID     1024
#define GC      5120          // 5*HID gate columns
#define OC      6144          // GC + HID (g then proj)
#define NCLS    151
#define MBn     16            // nodes per chunk (register tile)
#define XSTR    20            // smem stride (float4-aligned)
#define NBLK    48            // 6144 / 128 column blocks
#define KSPLIT  16            // one warp per k-slice
#define SMEMB   (XDIM * XSTR * 4)   // 179840 bytes dynamic smem

// ----- device scratch (static; no allocations anywhere) --------------------
__device__ float g_h[NMAX * HID];
__device__ float g_c[NMAX * HID];
__device__ float g_pe[NMAX * EMB];
__device__ float g_g[NMAX * OC];
__device__ int   g_commit[NMAX];
__device__ int   g_order[NMAX];
__device__ int   g_lvloff[NMAX + 1];
__device__ int   g_choff[NMAX + 1];
__device__ int   g_chlist[NMAX];
__device__ int   g_nlev;
__device__ volatile unsigned g_gen;
__device__ unsigned g_cnt;

// ----- helpers --------------------------------------------------------------
__device__ __forceinline__ float sigf(float x) {
    return 1.0f / (1.0f + expf(-x));
}

// packed dual-fp32 fma: d = a*b + c on both lanes (exact fp32 numerics)
__device__ __forceinline__ float2 ffma2(float2 a, float2 b, float2 c) {
    unsigned long long ua = reinterpret_cast<unsigned long long&>(a);
    unsigned long long ub = reinterpret_cast<unsigned long long&>(b);
    unsigned long long uc = reinterpret_cast<unsigned long long&>(c);
    unsigned long long ud;
    asm("fma.rn.f32x2 %0, %1, %2, %3;" : "=l"(ud) : "l"(ua), "l"(ub), "l"(uc));
    return reinterpret_cast<float2&>(ud);
}

// Sense-reversing grid barrier. Safe: grid == #SMs, big smem forces 1 CTA/SM.
__device__ __forceinline__ void grid_sync() {
    __threadfence();
    __syncthreads();
    if (threadIdx.x == 0) {
        unsigned gen = g_gen;
        unsigned a = atomicAdd(&g_cnt, 1u);
        if (a == gridDim.x - 1u) {
            g_cnt = 0u;
            __threadfence();
            g_gen = gen + 1u;
        } else {
            while (g_gen == gen) { __nanosleep(64); }
        }
    }
    __syncthreads();
}

// One k-step: 4x LDS.128 broadcast of x (16 nodes), 32 FFMA2 into 8x4 accs.
__device__ __forceinline__ void stepk(const float4 w, const float* __restrict__ xrow,
                                      float2 acc[8][4])
{
    float2 wd0 = make_float2(w.x, w.x);
    float2 wd1 = make_float2(w.y, w.y);
    float2 wd2 = make_float2(w.z, w.z);
    float2 wd3 = make_float2(w.w, w.w);
    const float4* xr = reinterpret_cast<const float4*>(xrow);
    float4 a = xr[0], b = xr[1], c = xr[2], d = xr[3];
    float2 xp[8] = { {a.x,a.y},{a.z,a.w},{b.x,b.y},{b.z,b.w},
                     {c.x,c.y},{c.z,c.w},{d.x,d.y},{d.z,d.w} };
#pragma unroll
    for (int p = 0; p < 8; ++p) {
        acc[p][0] = ffma2(xp[p], wd0, acc[p][0]);
        acc[p][1] = ffma2(xp[p], wd1, acc[p][1]);
        acc[p][2] = ffma2(xp[p], wd2, acc[p][2]);
        acc[p][3] = ffma2(xp[p], wd3, acc[p][3]);
    }
}

// Software-pipelined rank-1 update pass: prefetch depth 4 on W rows.
__device__ __forceinline__ void pass_accum2(
    const float* __restrict__ Wb,   // pre-offset by column
    int stride,                      // W row stride in floats
    const float* __restrict__ xs,    // smem staged [k][XSTR]
    int k0, int k1,
    float2 acc[8][4])
{
    const int nk = k1 - k0;
    const float* wl = Wb + (size_t)k0 * stride;       // load cursor
    const float* xc = xs + (size_t)k0 * XSTR;         // compute cursor
    const int kq = nk & ~3;

    if (kq) {
        float4 w0 = *reinterpret_cast<const float4*>(wl);
        float4 w1 = *reinterpret_cast<const float4*>(wl + stride);
        float4 w2 = *reinterpret_cast<const float4*>(wl + 2 * stride);
        float4 w3 = *reinterpret_cast<const float4*>(wl + 3 * stride);
        wl += (size_t)4 * stride;
        for (int b = 4; b < kq; b += 4) {
            stepk(w0, xc, acc); w0 = *reinterpret_cast<const float4*>(wl);              xc += XSTR;
            stepk(w1, xc, acc); w1 = *reinterpret_cast<const float4*>(wl + stride);     xc += XSTR;
            stepk(w2, xc, acc); w2 = *reinterpret_cast<const float4*>(wl + 2 * stride); xc += XSTR;
            stepk(w3, xc, acc); w3 = *reinterpret_cast<const float4*>(wl + 3 * stride); xc += XSTR;
            wl += (size_t)4 * stride;
        }
        stepk(w0, xc, acc); xc += XSTR;
        stepk(w1, xc, acc); xc += XSTR;
        stepk(w2, xc, acc); xc += XSTR;
        stepk(w3, xc, acc); xc += XSTR;
    }
    for (int r = kq; r < nk; ++r) {
        float4 w = *reinterpret_cast<const float4*>(wl);
        wl += stride;
        stepk(w, xc, acc);
        xc += XSTR;
    }
}

// ----- the persistent kernel -------------------------------------------------
__global__ void __launch_bounds__(NT, 1)
tree_lstm_kernel(const float* __restrict__ features,
                 const int*   __restrict__ parent,
                 const int*   __restrict__ bsz_ptr,
                 const float* __restrict__ W_px,   const float* __restrict__ b_px,
                 const float* __restrict__ W_iofux,const float* __restrict__ b_iofux,
                 const float* __restrict__ W_iofuh,const float* __restrict__ b_iofuh,
                 const float* __restrict__ W_out,  const float* __restrict__ b_out,
                 const float* __restrict__ embed,
                 float* __restrict__ out,
                 int n, long long out_size)
{
    extern __shared__ float smf[];
    const int tid = threadIdx.x;
    const int B = bsz_ptr ? bsz_ptr[0] : 8;

    // ================= PREP (CTA 0) =================
    if (blockIdx.x == 0) {
        int* si  = reinterpret_cast<int*>(smf);
        int* anc = si;
        int* lv  = si + 1024;
        int* cnt = si + 2048;
        int* cur = si + 3072;

        for (int i = tid; i < n; i += NT) {
            int p = parent[i];
            anc[i] = p;
            lv[i]  = (p >= 0) ? 1 : 0;
        }
        __syncthreads();

        for (int it = 0; it < 10; ++it) {     // pointer-doubling depth
            int ra[2], rl[2];
            int q = 0;
            for (int i = tid; i < n; i += NT, ++q) {
                int a = anc[i];
                rl[q] = (a >= 0) ? lv[a]  : 0;
                ra[q] = (a >= 0) ? anc[a] : -1;
            }
            __syncthreads();
            q = 0;
            for (int i = tid; i < n; i += NT, ++q) {
                lv[i]  += rl[q];
                anc[i]  = ra[q];
            }
            __syncthreads();
        }

        for (int i = tid; i < n; i += NT) cnt[i] = 0;
        if (tid == 0) si[4096] = 0;
        __syncthreads();
        int mx = 0;
        for (int i = tid; i < n; i += NT) {
            atomicAdd(&cnt[lv[i]], 1);
            if (lv[i] > mx) mx = lv[i];
        }
        atomicMax(&si[4096], mx);
        __syncthreads();
        int nlev = si[4096] + 1;

        if (tid == 0) {
            int s0 = 0;
            for (int l = 0; l < nlev; ++l) { g_lvloff[l] = s0; cur[l] = s0; s0 += cnt[l]; }
            g_lvloff[nlev] = s0;
            g_nlev = nlev;
        }
        __syncthreads();
        for (int i = tid; i < n; i += NT) {
            int pos = atomicAdd(&cur[lv[i]], 1);
            g_order[pos] = i;
        }
        __syncthreads();

        // children CSR
        for (int i = tid; i < n; i += NT) cnt[i] = 0;
        __syncthreads();
        for (int i = tid; i < n; i += NT) {
            int p = parent[i];
            if (p >= 0) atomicAdd(&cnt[p], 1);
        }
        __syncthreads();
        if (tid == 0) {
            int s0 = 0;
            for (int i = 0; i < n; ++i) { g_choff[i] = s0; cur[i] = s0; s0 += cnt[i]; }
            g_choff[n] = s0;
        }
        __syncthreads();
        for (int i = tid; i < n; i += NT) {
            int p = parent[i];
            if (p >= 0) {
                int e = atomicAdd(&cur[p], 1);
                g_chlist[e] = i;
            }
        }
        for (int i = tid; i < n; i += NT) {
            if (parent[i] < 0)
                for (int d = 0; d < EMB; ++d)
                    g_pe[(size_t)i * EMB + d] = embed[d];
        }
    }
    grid_sync();

    const int nlev = g_nlev;

    // ================= LEVEL LOOP =================
    for (int lev = 0; lev < nlev; ++lev) {
        const int lo = g_lvloff[lev];
        const int hi = g_lvloff[lev + 1];
        const int W  = hi - lo;

        // ---------- stage B: batched GEMVs ----------
        const int chunks = (W + MBn - 1) / MBn;
        const int ntasks = NBLK * chunks;
        for (int task = blockIdx.x; task < ntasks; task += gridDim.x) {
            const int cb    = task % NBLK;
            const int chunk = task / NBLK;
            const int base  = lo + chunk * MBn;
            float* xs = smf;

            // stage x = [features | pe], transposed: xs[k*XSTR + m] (div-free)
            {
                int m = 0, k = tid;
                int slot = base; if (slot > hi - 1) slot = hi - 1;
                int node = g_order[slot];
                while (m < MBn) {
                    float v = (k < INDIM)
                                ? features[(size_t)node * INDIM + k]
                                : g_pe[(size_t)node * EMB + (k - INDIM)];
                    xs[k * XSTR + m] = v;
                    k += NT;
                    if (k >= XDIM) {
                        k -= XDIM; ++m;
                        if (m < MBn) {
                            slot = base + m; if (slot > hi - 1) slot = hi - 1;
                            node = g_order[slot];
                        }
                    }
                }
            }
            __syncthreads();

            const int colt = tid & 31;
            const int kp   = tid >> 5;            // warp id == k-slice
            float2 acc[8][4];
#pragma unroll
            for (int p = 0; p < 8; ++p)
#pragma unroll
                for (int c = 0; c < 4; ++c) acc[p][c] = make_float2(0.f, 0.f);

            const float* Wb;
            int stride;
            if (cb < 40) { stride = GC;  Wb = W_iofux + cb * 128 + colt * 4; }
            else         { stride = HID; Wb = W_px + (cb - 40) * 128 + colt * 4; }

            {   // x pass: K = 2248 split over 16 warps
                int k0 = (kp * XDIM) / KSPLIT;
                int k1 = ((kp + 1) * XDIM) / KSPLIT;
                pass_accum2(Wb, stride, xs, k0, k1, acc);
            }

            if (cb < 40) {
                __syncthreads();
                // restage ph = h[parent] (0 for roots), div-free
                {
                    int m = 0, k = tid;
                    int slot = base; if (slot > hi - 1) slot = hi - 1;
                    int node = g_order[slot];
                    int par  = parent[node];
                    while (m < MBn) {
                        xs[k * XSTR + m] = (par >= 0) ? g_h[(size_t)par * HID + k] : 0.0f;
                        k += NT;
                        if (k >= HID) {
                            k -= HID; ++m;
                            if (m < MBn) {
                                slot = base + m; if (slot > hi - 1) slot = hi - 1;
                                node = g_order[slot];
                                par  = parent[node];
                            }
                        }
                    }
                }
                __syncthreads();
                int k0 = kp * (HID / KSPLIT);
                pass_accum2(W_iofuh + cb * 128 + colt * 4, GC, xs,
                            k0, k0 + HID / KSPLIT, acc);
            }

            // k-split reduction through smem (overlaps xs region)
            __syncthreads();
            float* red = smf;
#pragma unroll
            for (int p = 0; p < 8; ++p) {
                float4 lo4 = make_float4(acc[p][0].x, acc[p][1].x, acc[p][2].x, acc[p][3].x);
                float4 hi4 = make_float4(acc[p][0].y, acc[p][1].y, acc[p][2].y, acc[p][3].y);
                *reinterpret_cast<float4*>(red + kp * 2048 + (2 * p)     * 128 + colt * 4) = lo4;
                *reinterpret_cast<float4*>(red + kp * 2048 + (2 * p + 1) * 128 + colt * 4) = hi4;
            }
            __syncthreads();

            {   // each thread reduces exactly one float4 output
                const int m  = tid >> 5;
                const int cg = tid & 31;
                float4 s = make_float4(0.f, 0.f, 0.f, 0.f);
#pragma unroll
                for (int p = 0; p < KSPLIT; ++p) {
                    float4 v = *reinterpret_cast<const float4*>(
                        red + p * 2048 + m * 128 + cg * 4);
                    s.x += v.x; s.y += v.y; s.z += v.z; s.w += v.w;
                }
                int gcol; float4 bb;
                if (cb < 40) {
                    gcol = cb * 128 + cg * 4;
                    float4 b1 = *reinterpret_cast<const float4*>(b_iofux + gcol);
                    float4 b2 = *reinterpret_cast<const float4*>(b_iofuh + gcol);
                    bb = make_float4(b1.x + b2.x, b1.y + b2.y, b1.z + b2.z, b1.w + b2.w);
                } else {
                    int pcol = (cb - 40) * 128 + cg * 4;
                    bb   = *reinterpret_cast<const float4*>(b_px + pcol);
                    gcol = GC + pcol;
                }
                s.x += bb.x; s.y += bb.y; s.z += bb.z; s.w += bb.w;
                int slot = base + m; if (slot > hi - 1) slot = hi - 1;
                int node = g_order[slot];
                *reinterpret_cast<float4*>(g_g + (size_t)node * OC + gcol) = s;
            }
            __syncthreads();   // protect red before next task's staging
        }
        grid_sync();

        // ---------- stage CD: gates + output head, one CTA per node ----------
        for (int s = blockIdx.x; s < W; s += gridDim.x) {
            const int node = g_order[lo + s];
            const int par  = parent[node];
            const float* grow = g_g + (size_t)node * OC;
            float* hb   = smf;              // h_final, 1024 floats
            float* part = smf + HID;        // 512 partials for W_out GEMV
            float* db   = smf + HID + 512;  // dist, 151 floats
            int*   cms  = reinterpret_cast<int*>(smf) + HID + 512 + 256;

            const int j = tid * 2;          // 512*2 == 1024
            float2 ig2 = *reinterpret_cast<const float2*>(grow + j);
            float2 og2 = *reinterpret_cast<const float2*>(grow + HID + j);
            float2 fg2 = *reinterpret_cast<const float2*>(grow + 2 * HID + j);
            float2 ug2 = *reinterpret_cast<const float2*>(grow + 3 * HID + j);
            float2 rg2 = *reinterpret_cast<const float2*>(grow + 4 * HID + j);
            float2 pj2 = *reinterpret_cast<const float2*>(grow + 5 * HID + j);
            float2 pc2 = make_float2(0.f, 0.f);
            if (par >= 0)
                pc2 = *reinterpret_cast<const float2*>(g_c + (size_t)par * HID + j);

            float2 c2, hf2;
            {
                float iS, oS, fS, rS, cv, hv;
#define ELT(CC, HH, IG, OG, FG, UG, RG, PJ, PC)            \
                iS = sigf(IG); oS = sigf(OG); fS = sigf(FG); rS = sigf(RG); \
                cv = iS * tanhf(UG) + fS * (PC);           \
                hv = oS * tanhf(cv);                       \
                CC = cv; HH = rS * hv + (1.0f - rS) * (PJ);
                ELT(c2.x, hf2.x, ig2.x, og2.x, fg2.x, ug2.x, rg2.x, pj2.x, pc2.x)
                ELT(c2.y, hf2.y, ig2.y, og2.y, fg2.y, ug2.y, rg2.y, pj2.y, pc2.y)
#undef ELT
            }
            *reinterpret_cast<float2*>(g_c + (size_t)node * HID + j) = c2;
            *reinterpret_cast<float2*>(g_h + (size_t)node * HID + j) = hf2;
            *reinterpret_cast<float2*>(hb + j) = hf2;
            __syncthreads();

            // dist = h_final @ W_out + b_out ; 2-way k-split, 4 accumulators
            {
                const int c   = tid & 255;
                const int seg = tid >> 8;
                if (c < NCLS) {
                    const float* wc = W_out + c;
                    const int k0 = seg * 512;
                    float a0 = (seg == 0) ? b_out[c] : 0.0f;
                    float a1 = 0.f, a2 = 0.f, a3 = 0.f;
#pragma unroll 4
                    for (int k = k0; k < k0 + 512; k += 4) {
                        a0 = fmaf(hb[k],     wc[(size_t)(k)     * NCLS], a0);
                        a1 = fmaf(hb[k + 1], wc[(size_t)(k + 1) * NCLS], a1);
                        a2 = fmaf(hb[k + 2], wc[(size_t)(k + 2) * NCLS], a2);
                        a3 = fmaf(hb[k + 3], wc[(size_t)(k + 3) * NCLS], a3);
                    }
                    part[seg * 256 + c] = (a0 + a1) + (a2 + a3);
                }
            }
            __syncthreads();
            if (tid < NCLS) {
                float a = part[tid] + part[256 + tid];
                db[tid] = a;
                if (node >= B) {
                    size_t off = (size_t)(node - B) * NCLS + tid;
                    if (off < (size_t)out_size) out[off] = a;
                }
            }
            __syncthreads();

            // warp-parallel argmax over dist[1:], first-max semantics
            if (tid < 32) {
                float best = -3.4e38f; int bi = NCLS;
                for (int q = 1 + tid; q < NCLS; q += 32) {
                    float v = db[q];
                    if (v > best) { best = v; bi = q; }
                }
#pragma unroll
                for (int off = 16; off > 0; off >>= 1) {
                    float ov = __shfl_down_sync(0xffffffffu, best, off);
                    int   oi = __shfl_down_sync(0xffffffffu, bi, off);
                    if (ov > best || (ov == best && oi < bi)) { best = ov; bi = oi; }
                }
                if (tid == 0) { g_commit[node] = bi; cms[0] = bi; }
            }
            __syncthreads();

            // scatter embed[commit] into children's pe slots
            const int cm = cms[0];
            const int cs = g_choff[node];
            const int ce = g_choff[node + 1];
            const int tot = (ce - cs) * EMB;
            const float* erow = embed + (size_t)cm * EMB;
            for (int e = tid; e < tot; e += NT) {
                int q = e / EMB;
                int d = e - q * EMB;
                int ch = g_chlist[cs + q];
                g_pe[(size_t)ch * EMB + d] = erow[d];
            }
            __syncthreads();
        }
        grid_sync();
    }

    // ================= commitments tail =================
    const int NBo = n - B;
    for (int jj = blockIdx.x * NT + tid; jj < n; jj += gridDim.x * NT) {
        size_t off = (size_t)NBo * NCLS + jj;
        if (off < (size_t)out_size) {
            float v = (jj < NBo) ? (float)g_commit[B + jj] : 0.0f;
            out[off] = v;
        }
    }
}

// ----- host launcher ----------------------------------------------------------
extern "C" void kernel_launch(void* const* d_in, const int* in_sizes, int n_in,
                              void* d_out, int out_size)
{
    const float* features = (const float*)d_in[0];
    const int*   parent   = (const int*)  d_in[1];

    const int* bptr = nullptr;
    int base = 2;
    if (n_in >= 12) { bptr = (const int*)d_in[2]; base = 3; }

    const float* W_px    = (const float*)d_in[base + 0];
    const float* b_px    = (const float*)d_in[base + 1];
    const float* W_iofux = (const float*)d_in[base + 2];
    const float* b_iofux = (const float*)d_in[base + 3];
    const float* W_iofuh = (const float*)d_in[base + 4];
    const float* b_iofuh = (const float*)d_in[base + 5];
    const float* W_out   = (const float*)d_in[base + 6];
    const float* b_out   = (const float*)d_in[base + 7];
    const float* embed   = (const float*)d_in[base + 8];

    int n = in_sizes[1];
    if (n > NMAX) n = NMAX;

    int dev = 0, sms = 0;
    cudaGetDevice(&dev);
    cudaDeviceGetAttribute(&sms, cudaDevAttrMultiProcessorCount, dev);
    if (sms <= 0) sms = 148;

    cudaFuncSetAttribute(tree_lstm_kernel,
                         cudaFuncAttributeMaxDynamicSharedMemorySize, SMEMB);

    tree_lstm_kernel<<<sms, NT, SMEMB>>>(
        features, parent, bptr,
        W_px, b_px, W_iofux, b_iofux, W_iofuh, b_iofuh,
        W_out, b_out, embed,
        (float*)d_out, n, (long long)out_size);
}

// round 9
// speedup vs baseline: 2.1956x; 1.1848x over previous
#include <cuda_runtime.h>
#include <cstdint>
#include <cstddef>

// ---------------------------------------------------------------------------
// DecoderTreeLSTM — level-parallel persistent kernel, round 8
//   * 64-node chunks (4x arithmetic intensity on weight panels)
//   * K split across tasks (KS=3) -> 144 tasks/level = one 97% wave
//   * partial-g buffers summed in CD stage
//   * same FFMA2 inner loop (16 nodes x 4 cols per warp, 4 k-quarters/CTA)
// ---------------------------------------------------------------------------

#define NT      512
#define NMAX    1024
#define INDIM   2048
#define EMB     200
#define XDIM    2248          // INDIM + EMB
#define HID     1024
#define GC      5120          // 5*HID gate columns
#define OC      6144          // GC + HID (g then proj)
#define NCLS    151
#define CH      64            // nodes per chunk
#define NSTR    68            // smem row stride (floats), 16B-aligned
#define NBLK    48            // 6144 / 128 column blocks
#define KS      3             // cross-task k-split
#define MAXROWS 750           // max staged k-rows = ceil(XDIM/KS)
#define SMEMB   (MAXROWS * NSTR * 4)   // 204000 bytes dynamic smem

// ----- device scratch (static; no allocations anywhere) --------------------
__device__ float g_h[NMAX * HID];
__device__ float g_c[NMAX * HID];
__device__ float g_pe[NMAX * EMB];
__device__ float g_part[KS][NMAX * OC];   // partial g per k-split
__device__ int   g_commit[NMAX];
__device__ int   g_order[NMAX];
__device__ int   g_lvloff[NMAX + 1];
__device__ int   g_choff[NMAX + 1];
__device__ int   g_chlist[NMAX];
__device__ int   g_nlev;
__device__ volatile unsigned g_gen;
__device__ unsigned g_cnt;

// ----- helpers --------------------------------------------------------------
__device__ __forceinline__ float sigf(float x) {
    return 1.0f / (1.0f + expf(-x));
}

__device__ __forceinline__ float2 ffma2(float2 a, float2 b, float2 c) {
    unsigned long long ua = reinterpret_cast<unsigned long long&>(a);
    unsigned long long ub = reinterpret_cast<unsigned long long&>(b);
    unsigned long long uc = reinterpret_cast<unsigned long long&>(c);
    unsigned long long ud;
    asm("fma.rn.f32x2 %0, %1, %2, %3;" : "=l"(ud) : "l"(ua), "l"(ub), "l"(uc));
    return reinterpret_cast<float2&>(ud);
}

// Sense-reversing grid barrier. Safe: grid == #SMs, big smem forces 1 CTA/SM.
__device__ __forceinline__ void grid_sync() {
    __threadfence();
    __syncthreads();
    if (threadIdx.x == 0) {
        unsigned gen = g_gen;
        unsigned a = atomicAdd(&g_cnt, 1u);
        if (a == gridDim.x - 1u) {
            g_cnt = 0u;
            __threadfence();
            g_gen = gen + 1u;
        } else {
            while (g_gen == gen) { __nanosleep(64); }
        }
    }
    __syncthreads();
}

// One k-step: 4x LDS.128 broadcast of x (16 nodes), 32 FFMA2 into 8x4 accs.
__device__ __forceinline__ void stepk(const float4 w, const float* __restrict__ xrow,
                                      float2 acc[8][4])
{
    float2 wd0 = make_float2(w.x, w.x);
    float2 wd1 = make_float2(w.y, w.y);
    float2 wd2 = make_float2(w.z, w.z);
    float2 wd3 = make_float2(w.w, w.w);
    const float4* xr = reinterpret_cast<const float4*>(xrow);
    float4 a = xr[0], b = xr[1], c = xr[2], d = xr[3];
    float2 xp[8] = { {a.x,a.y},{a.z,a.w},{b.x,b.y},{b.z,b.w},
                     {c.x,c.y},{c.z,c.w},{d.x,d.y},{d.z,d.w} };
#pragma unroll
    for (int p = 0; p < 8; ++p) {
        acc[p][0] = ffma2(xp[p], wd0, acc[p][0]);
        acc[p][1] = ffma2(xp[p], wd1, acc[p][1]);
        acc[p][2] = ffma2(xp[p], wd2, acc[p][2]);
        acc[p][3] = ffma2(xp[p], wd3, acc[p][3]);
    }
}

// Pipelined rank-1 update pass over absolute W rows [ka, kb); x rows are
// (k - krel0)*NSTR relative to the staged slice, xbase pre-offset by node grp.
__device__ __forceinline__ void pass_accum2(
    const float* __restrict__ Wb, int stride,
    const float* __restrict__ xbase, int krel0,
    int ka, int kb,
    float2 acc[8][4])
{
    const int nk = kb - ka;
    const float* wl = Wb + (size_t)ka * stride;
    const float* xc = xbase + (size_t)(ka - krel0) * NSTR;
    const int kq = nk & ~3;

    if (kq) {
        float4 w0 = *reinterpret_cast<const float4*>(wl);
        float4 w1 = *reinterpret_cast<const float4*>(wl + stride);
        float4 w2 = *reinterpret_cast<const float4*>(wl + 2 * stride);
        float4 w3 = *reinterpret_cast<const float4*>(wl + 3 * stride);
        wl += (size_t)4 * stride;
        for (int b = 4; b < kq; b += 4) {
            stepk(w0, xc, acc); w0 = *reinterpret_cast<const float4*>(wl);              xc += NSTR;
            stepk(w1, xc, acc); w1 = *reinterpret_cast<const float4*>(wl + stride);     xc += NSTR;
            stepk(w2, xc, acc); w2 = *reinterpret_cast<const float4*>(wl + 2 * stride); xc += NSTR;
            stepk(w3, xc, acc); w3 = *reinterpret_cast<const float4*>(wl + 3 * stride); xc += NSTR;
            wl += (size_t)4 * stride;
        }
        stepk(w0, xc, acc); xc += NSTR;
        stepk(w1, xc, acc); xc += NSTR;
        stepk(w2, xc, acc); xc += NSTR;
        stepk(w3, xc, acc); xc += NSTR;
    }
    for (int r = kq; r < nk; ++r) {
        float4 w = *reinterpret_cast<const float4*>(wl);
        wl += stride;
        stepk(w, xc, acc);
        xc += NSTR;
    }
}

// ----- the persistent kernel -------------------------------------------------
__global__ void __launch_bounds__(NT, 1)
tree_lstm_kernel(const float* __restrict__ features,
                 const int*   __restrict__ parent,
                 const int*   __restrict__ bsz_ptr,
                 const float* __restrict__ W_px,   const float* __restrict__ b_px,
                 const float* __restrict__ W_iofux,const float* __restrict__ b_iofux,
                 const float* __restrict__ W_iofuh,const float* __restrict__ b_iofuh,
                 const float* __restrict__ W_out,  const float* __restrict__ b_out,
                 const float* __restrict__ embed,
                 float* __restrict__ out,
                 int n, long long out_size)
{
    extern __shared__ float smf[];
    const int tid = threadIdx.x;
    const int B = bsz_ptr ? bsz_ptr[0] : 8;

    // ================= PREP (CTA 0) =================
    if (blockIdx.x == 0) {
        int* si  = reinterpret_cast<int*>(smf);
        int* anc = si;
        int* lv  = si + 1024;
        int* cnt = si + 2048;
        int* cur = si + 3072;

        for (int i = tid; i < n; i += NT) {
            int p = parent[i];
            anc[i] = p;
            lv[i]  = (p >= 0) ? 1 : 0;
        }
        __syncthreads();

        for (int it = 0; it < 10; ++it) {     // pointer-doubling depth
            int ra[2], rl[2];
            int q = 0;
            for (int i = tid; i < n; i += NT, ++q) {
                int a = anc[i];
                rl[q] = (a >= 0) ? lv[a]  : 0;
                ra[q] = (a >= 0) ? anc[a] : -1;
            }
            __syncthreads();
            q = 0;
            for (int i = tid; i < n; i += NT, ++q) {
                lv[i]  += rl[q];
                anc[i]  = ra[q];
            }
            __syncthreads();
        }

        for (int i = tid; i < n; i += NT) cnt[i] = 0;
        if (tid == 0) si[4096] = 0;
        __syncthreads();
        int mx = 0;
        for (int i = tid; i < n; i += NT) {
            atomicAdd(&cnt[lv[i]], 1);
            if (lv[i] > mx) mx = lv[i];
        }
        atomicMax(&si[4096], mx);
        __syncthreads();
        int nlev = si[4096] + 1;

        if (tid == 0) {
            int s0 = 0;
            for (int l = 0; l < nlev; ++l) { g_lvloff[l] = s0; cur[l] = s0; s0 += cnt[l]; }
            g_lvloff[nlev] = s0;
            g_nlev = nlev;
        }
        __syncthreads();
        for (int i = tid; i < n; i += NT) {
            int pos = atomicAdd(&cur[lv[i]], 1);
            g_order[pos] = i;
        }
        __syncthreads();

        // children CSR
        for (int i = tid; i < n; i += NT) cnt[i] = 0;
        __syncthreads();
        for (int i = tid; i < n; i += NT) {
            int p = parent[i];
            if (p >= 0) atomicAdd(&cnt[p], 1);
        }
        __syncthreads();
        if (tid == 0) {
            int s0 = 0;
            for (int i = 0; i < n; ++i) { g_choff[i] = s0; cur[i] = s0; s0 += cnt[i]; }
            g_choff[n] = s0;
        }
        __syncthreads();
        for (int i = tid; i < n; i += NT) {
            int p = parent[i];
            if (p >= 0) {
                int e = atomicAdd(&cur[p], 1);
                g_chlist[e] = i;
            }
        }
        for (int i = tid; i < n; i += NT) {
            if (parent[i] < 0)
                for (int d = 0; d < EMB; ++d)
                    g_pe[(size_t)i * EMB + d] = embed[d];
        }
    }
    grid_sync();

    const int nlev = g_nlev;

    // ================= LEVEL LOOP =================
    for (int lev = 0; lev < nlev; ++lev) {
        const int lo = g_lvloff[lev];
        const int hi = g_lvloff[lev + 1];
        const int W  = hi - lo;

        // ---------- stage B ----------
        const int chunks = (W + CH - 1) / CH;
        const int ntasks = NBLK * KS * chunks;
        for (int task = blockIdx.x; task < ntasks; task += gridDim.x) {
            const int cb    = task % NBLK;
            const int r     = task / NBLK;
            const int ks    = r % KS;
            const int chunk = r / KS;
            const int base  = lo + chunk * CH;
            float* xs = smf;

            const int k0x = (ks * XDIM) / KS;
            const int k1x = ((ks + 1) * XDIM) / KS;

            // ---- stage x slice [k0x,k1x) for 64 nodes, 4-node unroll ----
            {
                for (int mq = 0; mq < CH; mq += 4) {
                    int s0 = base + mq;     if (s0 > hi - 1) s0 = hi - 1;
                    int s1 = base + mq + 1; if (s1 > hi - 1) s1 = hi - 1;
                    int s2 = base + mq + 2; if (s2 > hi - 1) s2 = hi - 1;
                    int s3 = base + mq + 3; if (s3 > hi - 1) s3 = hi - 1;
                    int n0 = g_order[s0], n1 = g_order[s1];
                    int n2 = g_order[s2], n3 = g_order[s3];
                    for (int k = k0x + tid; k < k1x; k += NT) {
                        float v0, v1, v2, v3;
                        if (k < INDIM) {
                            v0 = features[(size_t)n0 * INDIM + k];
                            v1 = features[(size_t)n1 * INDIM + k];
                            v2 = features[(size_t)n2 * INDIM + k];
                            v3 = features[(size_t)n3 * INDIM + k];
                        } else {
                            int d = k - INDIM;
                            v0 = g_pe[(size_t)n0 * EMB + d];
                            v1 = g_pe[(size_t)n1 * EMB + d];
                            v2 = g_pe[(size_t)n2 * EMB + d];
                            v3 = g_pe[(size_t)n3 * EMB + d];
                        }
                        float* row = xs + (size_t)(k - k0x) * NSTR + mq;
                        row[0] = v0; row[1] = v1; row[2] = v2; row[3] = v3;
                    }
                }
            }
            __syncthreads();

            const int colt = tid & 31;
            const int wid  = tid >> 5;
            const int ng   = wid & 3;          // node group: nodes ng*16..+16
            const int kq   = wid >> 2;         // intra-CTA k quarter
            float2 acc[8][4];
#pragma unroll
            for (int p = 0; p < 8; ++p)
#pragma unroll
                for (int c = 0; c < 4; ++c) acc[p][c] = make_float2(0.f, 0.f);

            const float* Wb;
            int stride;
            if (cb < 40) { stride = GC;  Wb = W_iofux + cb * 128 + colt * 4; }
            else         { stride = HID; Wb = W_px + (cb - 40) * 128 + colt * 4; }

            {   // x pass
                int len = k1x - k0x;
                int ka = k0x + (len * kq) / 4;
                int kb = k0x + (len * (kq + 1)) / 4;
                pass_accum2(Wb, stride, xs + ng * 16, k0x, ka, kb, acc);
            }

            if (cb < 40) {
                const int p0 = (ks * HID) / KS;
                const int p1 = ((ks + 1) * HID) / KS;
                __syncthreads();
                // ---- stage ph slice (0 for roots), 4-node unroll ----
                for (int mq = 0; mq < CH; mq += 4) {
                    int s0 = base + mq;     if (s0 > hi - 1) s0 = hi - 1;
                    int s1 = base + mq + 1; if (s1 > hi - 1) s1 = hi - 1;
                    int s2 = base + mq + 2; if (s2 > hi - 1) s2 = hi - 1;
                    int s3 = base + mq + 3; if (s3 > hi - 1) s3 = hi - 1;
                    int pa = parent[g_order[s0]], pb = parent[g_order[s1]];
                    int pc = parent[g_order[s2]], pd = parent[g_order[s3]];
                    for (int k = p0 + tid; k < p1; k += NT) {
                        float v0 = (pa >= 0) ? g_h[(size_t)pa * HID + k] : 0.0f;
                        float v1 = (pb >= 0) ? g_h[(size_t)pb * HID + k] : 0.0f;
                        float v2 = (pc >= 0) ? g_h[(size_t)pc * HID + k] : 0.0f;
                        float v3 = (pd >= 0) ? g_h[(size_t)pd * HID + k] : 0.0f;
                        float* row = xs + (size_t)(k - p0) * NSTR + mq;
                        row[0] = v0; row[1] = v1; row[2] = v2; row[3] = v3;
                    }
                }
                __syncthreads();
                int len = p1 - p0;
                int ka = p0 + (len * kq) / 4;
                int kb = p0 + (len * (kq + 1)) / 4;
                pass_accum2(W_iofuh + cb * 128 + colt * 4, GC,
                            xs + ng * 16, p0, ka, kb, acc);
            }

            // ---- reduce 4 k-quarters through smem (overlay xs) ----
            __syncthreads();
            float* red = smf;   // [4 quarters][64 nodes][128 cols]
#pragma unroll
            for (int p = 0; p < 8; ++p) {
                float4 lo4 = make_float4(acc[p][0].x, acc[p][1].x, acc[p][2].x, acc[p][3].x);
                float4 hi4 = make_float4(acc[p][0].y, acc[p][1].y, acc[p][2].y, acc[p][3].y);
                int rowA = kq * 64 + ng * 16 + 2 * p;
                *reinterpret_cast<float4*>(red + (size_t)rowA       * 128 + colt * 4) = lo4;
                *reinterpret_cast<float4*>(red + (size_t)(rowA + 1) * 128 + colt * 4) = hi4;
            }
            __syncthreads();

            {   // 512 threads: node = tid>>3, 16 cols each
                const int m  = tid >> 3;
                const int c0 = (tid & 7) * 16;
                int slot = base + m; if (slot > hi - 1) slot = hi - 1;
                int node = g_order[slot];
                int gcol = (cb < 40) ? (cb * 128 + c0) : (GC + (cb - 40) * 128 + c0);
                float* dst = &g_part[ks][(size_t)node * OC + gcol];
#pragma unroll
                for (int i = 0; i < 4; ++i) {
                    float4 s = make_float4(0.f, 0.f, 0.f, 0.f);
#pragma unroll
                    for (int q = 0; q < 4; ++q) {
                        float4 v = *reinterpret_cast<const float4*>(
                            red + (size_t)(q * 64 + m) * 128 + c0 + i * 4);
                        s.x += v.x; s.y += v.y; s.z += v.z; s.w += v.w;
                    }
                    if (ks == 0) {
                        float4 bb;
                        if (cb < 40) {
                            float4 b1 = *reinterpret_cast<const float4*>(b_iofux + gcol + i * 4);
                            float4 b2 = *reinterpret_cast<const float4*>(b_iofuh + gcol + i * 4);
                            bb = make_float4(b1.x + b2.x, b1.y + b2.y, b1.z + b2.z, b1.w + b2.w);
                        } else {
                            bb = *reinterpret_cast<const float4*>(
                                b_px + (gcol - GC) + i * 4);
                        }
                        s.x += bb.x; s.y += bb.y; s.z += bb.z; s.w += bb.w;
                    }
                    *reinterpret_cast<float4*>(dst + i * 4) = s;
                }
            }
            __syncthreads();   // xs/red reuse on next task
        }
        grid_sync();

        // ---------- stage CD: gates + output head, one CTA per node ----------
        for (int s = blockIdx.x; s < W; s += gridDim.x) {
            const int node = g_order[lo + s];
            const int par  = parent[node];
            const float* q0 = g_part[0] + (size_t)node * OC;
            const float* q1 = g_part[1] + (size_t)node * OC;
            const float* q2 = g_part[2] + (size_t)node * OC;
            float* hb   = smf;              // h_final, 1024 floats
            float* part = smf + HID;        // 512 partials for W_out GEMV
            float* db   = smf + HID + 512;  // dist, 151 floats
            int*   cms  = reinterpret_cast<int*>(smf) + HID + 512 + 256;

            const int j = tid * 2;          // 512*2 == 1024
#define GSUM(OFF) make_float2( \
            q0[(OFF) + j] + q1[(OFF) + j] + q2[(OFF) + j], \
            q0[(OFF) + j + 1] + q1[(OFF) + j + 1] + q2[(OFF) + j + 1])
            float2 ig2 = GSUM(0);
            float2 og2 = GSUM(HID);
            float2 fg2 = GSUM(2 * HID);
            float2 ug2 = GSUM(3 * HID);
            float2 rg2 = GSUM(4 * HID);
            float2 pj2 = GSUM(5 * HID);
#undef GSUM
            float2 pc2 = make_float2(0.f, 0.f);
            if (par >= 0)
                pc2 = *reinterpret_cast<const float2*>(g_c + (size_t)par * HID + j);

            float2 c2, hf2;
            {
                float iS, oS, fS, rS, cv, hv;
#define ELT(CC, HH, IG, OG, FG, UG, RG, PJ, PC)            \
                iS = sigf(IG); oS = sigf(OG); fS = sigf(FG); rS = sigf(RG); \
                cv = iS * tanhf(UG) + fS * (PC);           \
                hv = oS * tanhf(cv);                       \
                CC = cv; HH = rS * hv + (1.0f - rS) * (PJ);
                ELT(c2.x, hf2.x, ig2.x, og2.x, fg2.x, ug2.x, rg2.x, pj2.x, pc2.x)
                ELT(c2.y, hf2.y, ig2.y, og2.y, fg2.y, ug2.y, rg2.y, pj2.y, pc2.y)
#undef ELT
            }
            *reinterpret_cast<float2*>(g_c + (size_t)node * HID + j) = c2;
            *reinterpret_cast<float2*>(g_h + (size_t)node * HID + j) = hf2;
            *reinterpret_cast<float2*>(hb + j) = hf2;
            __syncthreads();

            // dist = h_final @ W_out + b_out ; 2-way k-split, 4 accumulators
            {
                const int c   = tid & 255;
                const int seg = tid >> 8;
                if (c < NCLS) {
                    const float* wc = W_out + c;
                    const int k0 = seg * 512;
                    float a0 = (seg == 0) ? b_out[c] : 0.0f;
                    float a1 = 0.f, a2 = 0.f, a3 = 0.f;
#pragma unroll 4
                    for (int k = k0; k < k0 + 512; k += 4) {
                        a0 = fmaf(hb[k],     wc[(size_t)(k)     * NCLS], a0);
                        a1 = fmaf(hb[k + 1], wc[(size_t)(k + 1) * NCLS], a1);
                        a2 = fmaf(hb[k + 2], wc[(size_t)(k + 2) * NCLS], a2);
                        a3 = fmaf(hb[k + 3], wc[(size_t)(k + 3) * NCLS], a3);
                    }
                    part[seg * 256 + c] = (a0 + a1) + (a2 + a3);
                }
            }
            __syncthreads();
            if (tid < NCLS) {
                float a = part[tid] + part[256 + tid];
                db[tid] = a;
                if (node >= B) {
                    size_t off = (size_t)(node - B) * NCLS + tid;
                    if (off < (size_t)out_size) out[off] = a;
                }
            }
            __syncthreads();

            // warp-parallel argmax over dist[1:], first-max semantics
            if (tid < 32) {
                float best = -3.4e38f; int bi = NCLS;
                for (int q = 1 + tid; q < NCLS; q += 32) {
                    float v = db[q];
                    if (v > best) { best = v; bi = q; }
                }
#pragma unroll
                for (int off = 16; off > 0; off >>= 1) {
                    float ov = __shfl_down_sync(0xffffffffu, best, off);
                    int   oi = __shfl_down_sync(0xffffffffu, bi, off);
                    if (ov > best || (ov == best && oi < bi)) { best = ov; bi = oi; }
                }
                if (tid == 0) { g_commit[node] = bi; cms[0] = bi; }
            }
            __syncthreads();

            // scatter embed[commit] into children's pe slots
            const int cm = cms[0];
            const int cs = g_choff[node];
            const int ce = g_choff[node + 1];
            const int tot = (ce - cs) * EMB;
            const float* erow = embed + (size_t)cm * EMB;
            for (int e = tid; e < tot; e += NT) {
                int q = e / EMB;
                int d = e - q * EMB;
                int ch = g_chlist[cs + q];
                g_pe[(size_t)ch * EMB + d] = erow[d];
            }
            __syncthreads();
        }
        grid_sync();
    }

    // ================= commitments tail =================
    const int NBo = n - B;
    for (int jj = blockIdx.x * NT + tid; jj < n; jj += gridDim.x * NT) {
        size_t off = (size_t)NBo * NCLS + jj;
        if (off < (size_t)out_size) {
            float v = (jj < NBo) ? (float)g_commit[B + jj] : 0.0f;
            out[off] = v;
        }
    }
}

// ----- host launcher ----------------------------------------------------------
extern "C" void kernel_launch(void* const* d_in, const int* in_sizes, int n_in,
                              void* d_out, int out_size)
{
    const float* features = (const float*)d_in[0];
    const int*   parent   = (const int*)  d_in[1];

    const int* bptr = nullptr;
    int base = 2;
    if (n_in >= 12) { bptr = (const int*)d_in[2]; base = 3; }

    const float* W_px    = (const float*)d_in[base + 0];
    const float* b_px    = (const float*)d_in[base + 1];
    const float* W_iofux = (const float*)d_in[base + 2];
    const float* b_iofux = (const float*)d_in[base + 3];
    const float* W_iofuh = (const float*)d_in[base + 4];
    const float* b_iofuh = (const float*)d_in[base + 5];
    const float* W_out   = (const float*)d_in[base + 6];
    const float* b_out   = (const float*)d_in[base + 7];
    const float* embed   = (const float*)d_in[base + 8];

    int n = in_sizes[1];
    if (n > NMAX) n = NMAX;

    int dev = 0, sms = 0;
    cudaGetDevice(&dev);
    cudaDeviceGetAttribute(&sms, cudaDevAttrMultiProcessorCount, dev);
    if (sms <= 0) sms = 148;

    cudaFuncSetAttribute(tree_lstm_kernel,
                         cudaFuncAttributeMaxDynamicSharedMemorySize, SMEMB);

    tree_lstm_kernel<<<sms, NT, SMEMB>>>(
        features, parent, bptr,
        W_px, b_px, W_iofux, b_iofux, W_iofuh, b_iofuh,
        W_out, b_out, embed,
        (float*)d_out, n, (long long)out_size);
}

// round 10
// speedup vs baseline: 2.3290x; 1.0608x over previous
#include <cuda_runtime.h>
#include <cstdint>
#include <cstddef>

// ---------------------------------------------------------------------------
// DecoderTreeLSTM — level-parallel persistent kernel, round 9
//   * CH=32 node chunks (halved padding + halved wave quantum)
//   * balanced task set: gates KS=3 (1091 rows), proj KS=2 (1124 rows)
//     -> 136 equal-duration tasks per chunk = one 92% wave on 148 SMs
//   * 8-way intra-CTA k-split, red buffer [8][32][128]
// ---------------------------------------------------------------------------

#define NT      512
#define NMAX    1024
#define INDIM   2048
#define EMB     200
#define XDIM    2248          // INDIM + EMB
#define HID     1024
#define GC      5120          // 5*HID gate columns
#define OC      6144          // GC + HID (g then proj)
#define NCLS    151
#define CH      32            // nodes per chunk
#define NSTR    36            // smem row stride (floats), 16B-aligned
#define KS      3             // gate k-split (proj uses 2)
#define TPC     136           // tasks per chunk: 40*3 gates + 8*2 proj
#define MAXROWS 1124          // max staged k-rows (proj slice XDIM/2)
#define SMEMB   (MAXROWS * NSTR * 4)   // 161856 bytes dynamic smem

// ----- device scratch (static; no allocations anywhere) --------------------
__device__ float g_h[NMAX * HID];
__device__ float g_c[NMAX * HID];
__device__ float g_pe[NMAX * EMB];
__device__ float g_part[KS][NMAX * OC];   // partial g per k-split
__device__ int   g_commit[NMAX];
__device__ int   g_order[NMAX];
__device__ int   g_lvloff[NMAX + 1];
__device__ int   g_choff[NMAX + 1];
__device__ int   g_chlist[NMAX];
__device__ int   g_nlev;
__device__ volatile unsigned g_gen;
__device__ unsigned g_cnt;

// ----- helpers --------------------------------------------------------------
__device__ __forceinline__ float sigf(float x) {
    return 1.0f / (1.0f + expf(-x));
}

__device__ __forceinline__ float2 ffma2(float2 a, float2 b, float2 c) {
    unsigned long long ua = reinterpret_cast<unsigned long long&>(a);
    unsigned long long ub = reinterpret_cast<unsigned long long&>(b);
    unsigned long long uc = reinterpret_cast<unsigned long long&>(c);
    unsigned long long ud;
    asm("fma.rn.f32x2 %0, %1, %2, %3;" : "=l"(ud) : "l"(ua), "l"(ub), "l"(uc));
    return reinterpret_cast<float2&>(ud);
}

// Sense-reversing grid barrier. Safe: grid == #SMs, big smem forces 1 CTA/SM.
__device__ __forceinline__ void grid_sync() {
    __threadfence();
    __syncthreads();
    if (threadIdx.x == 0) {
        unsigned gen = g_gen;
        unsigned a = atomicAdd(&g_cnt, 1u);
        if (a == gridDim.x - 1u) {
            g_cnt = 0u;
            __threadfence();
            g_gen = gen + 1u;
        } else {
            while (g_gen == gen) { __nanosleep(64); }
        }
    }
    __syncthreads();
}

// One k-step: 4x LDS.128 broadcast of x (16 nodes), 32 FFMA2 into 8x4 accs.
__device__ __forceinline__ void stepk(const float4 w, const float* __restrict__ xrow,
                                      float2 acc[8][4])
{
    float2 wd0 = make_float2(w.x, w.x);
    float2 wd1 = make_float2(w.y, w.y);
    float2 wd2 = make_float2(w.z, w.z);
    float2 wd3 = make_float2(w.w, w.w);
    const float4* xr = reinterpret_cast<const float4*>(xrow);
    float4 a = xr[0], b = xr[1], c = xr[2], d = xr[3];
    float2 xp[8] = { {a.x,a.y},{a.z,a.w},{b.x,b.y},{b.z,b.w},
                     {c.x,c.y},{c.z,c.w},{d.x,d.y},{d.z,d.w} };
#pragma unroll
    for (int p = 0; p < 8; ++p) {
        acc[p][0] = ffma2(xp[p], wd0, acc[p][0]);
        acc[p][1] = ffma2(xp[p], wd1, acc[p][1]);
        acc[p][2] = ffma2(xp[p], wd2, acc[p][2]);
        acc[p][3] = ffma2(xp[p], wd3, acc[p][3]);
    }
}

// Pipelined rank-1 update over absolute W rows [ka, kb); x rows relative to
// staged slice start krel0; xbase pre-offset by node group.
__device__ __forceinline__ void pass_accum2(
    const float* __restrict__ Wb, int stride,
    const float* __restrict__ xbase, int krel0,
    int ka, int kb,
    float2 acc[8][4])
{
    const int nk = kb - ka;
    const float* wl = Wb + (size_t)ka * stride;
    const float* xc = xbase + (size_t)(ka - krel0) * NSTR;
    const int kq = nk & ~3;

    if (kq) {
        float4 w0 = *reinterpret_cast<const float4*>(wl);
        float4 w1 = *reinterpret_cast<const float4*>(wl + stride);
        float4 w2 = *reinterpret_cast<const float4*>(wl + 2 * stride);
        float4 w3 = *reinterpret_cast<const float4*>(wl + 3 * stride);
        wl += (size_t)4 * stride;
        for (int b = 4; b < kq; b += 4) {
            stepk(w0, xc, acc); w0 = *reinterpret_cast<const float4*>(wl);              xc += NSTR;
            stepk(w1, xc, acc); w1 = *reinterpret_cast<const float4*>(wl + stride);     xc += NSTR;
            stepk(w2, xc, acc); w2 = *reinterpret_cast<const float4*>(wl + 2 * stride); xc += NSTR;
            stepk(w3, xc, acc); w3 = *reinterpret_cast<const float4*>(wl + 3 * stride); xc += NSTR;
            wl += (size_t)4 * stride;
        }
        stepk(w0, xc, acc); xc += NSTR;
        stepk(w1, xc, acc); xc += NSTR;
        stepk(w2, xc, acc); xc += NSTR;
        stepk(w3, xc, acc); xc += NSTR;
    }
    for (int r = kq; r < nk; ++r) {
        float4 w = *reinterpret_cast<const float4*>(wl);
        wl += stride;
        stepk(w, xc, acc);
        xc += NSTR;
    }
}

// ----- the persistent kernel -------------------------------------------------
__global__ void __launch_bounds__(NT, 1)
tree_lstm_kernel(const float* __restrict__ features,
                 const int*   __restrict__ parent,
                 const int*   __restrict__ bsz_ptr,
                 const float* __restrict__ W_px,   const float* __restrict__ b_px,
                 const float* __restrict__ W_iofux,const float* __restrict__ b_iofux,
                 const float* __restrict__ W_iofuh,const float* __restrict__ b_iofuh,
                 const float* __restrict__ W_out,  const float* __restrict__ b_out,
                 const float* __restrict__ embed,
                 float* __restrict__ out,
                 int n, long long out_size)
{
    extern __shared__ float smf[];
    const int tid = threadIdx.x;
    const int B = bsz_ptr ? bsz_ptr[0] : 8;

    // ================= PREP (CTA 0) =================
    if (blockIdx.x == 0) {
        int* si  = reinterpret_cast<int*>(smf);
        int* anc = si;
        int* lv  = si + 1024;
        int* cnt = si + 2048;
        int* cur = si + 3072;

        for (int i = tid; i < n; i += NT) {
            int p = parent[i];
            anc[i] = p;
            lv[i]  = (p >= 0) ? 1 : 0;
        }
        __syncthreads();

        for (int it = 0; it < 10; ++it) {     // pointer-doubling depth
            int ra[2], rl[2];
            int q = 0;
            for (int i = tid; i < n; i += NT, ++q) {
                int a = anc[i];
                rl[q] = (a >= 0) ? lv[a]  : 0;
                ra[q] = (a >= 0) ? anc[a] : -1;
            }
            __syncthreads();
            q = 0;
            for (int i = tid; i < n; i += NT, ++q) {
                lv[i]  += rl[q];
                anc[i]  = ra[q];
            }
            __syncthreads();
        }

        for (int i = tid; i < n; i += NT) cnt[i] = 0;
        if (tid == 0) si[4096] = 0;
        __syncthreads();
        int mx = 0;
        for (int i = tid; i < n; i += NT) {
            atomicAdd(&cnt[lv[i]], 1);
            if (lv[i] > mx) mx = lv[i];
        }
        atomicMax(&si[4096], mx);
        __syncthreads();
        int nlev = si[4096] + 1;

        if (tid == 0) {
            int s0 = 0;
            for (int l = 0; l < nlev; ++l) { g_lvloff[l] = s0; cur[l] = s0; s0 += cnt[l]; }
            g_lvloff[nlev] = s0;
            g_nlev = nlev;
        }
        __syncthreads();
        for (int i = tid; i < n; i += NT) {
            int pos = atomicAdd(&cur[lv[i]], 1);
            g_order[pos] = i;
        }
        __syncthreads();

        // children CSR
        for (int i = tid; i < n; i += NT) cnt[i] = 0;
        __syncthreads();
        for (int i = tid; i < n; i += NT) {
            int p = parent[i];
            if (p >= 0) atomicAdd(&cnt[p], 1);
        }
        __syncthreads();
        if (tid == 0) {
            int s0 = 0;
            for (int i = 0; i < n; ++i) { g_choff[i] = s0; cur[i] = s0; s0 += cnt[i]; }
            g_choff[n] = s0;
        }
        __syncthreads();
        for (int i = tid; i < n; i += NT) {
            int p = parent[i];
            if (p >= 0) {
                int e = atomicAdd(&cur[p], 1);
                g_chlist[e] = i;
            }
        }
        for (int i = tid; i < n; i += NT) {
            if (parent[i] < 0)
                for (int d = 0; d < EMB; ++d)
                    g_pe[(size_t)i * EMB + d] = embed[d];
        }
    }
    grid_sync();

    const int nlev = g_nlev;

    // ================= LEVEL LOOP =================
    for (int lev = 0; lev < nlev; ++lev) {
        const int lo = g_lvloff[lev];
        const int hi = g_lvloff[lev + 1];
        const int W  = hi - lo;

        // ---------- stage B ----------
        const int chunks = (W + CH - 1) / CH;
        const int ntasks = TPC * chunks;
        for (int task = blockIdx.x; task < ntasks; task += gridDim.x) {
            const int t     = task % TPC;
            const int chunk = task / TPC;
            const int base  = lo + chunk * CH;
            float* xs = smf;

            int cb, ks, k0x, k1x;
            bool is_gate;
            if (t < 120) {                 // gate tasks: 40 col-blocks x KS=3
                is_gate = true;
                cb = t % 40;
                ks = t / 40;
                k0x = (ks * XDIM) / 3;
                k1x = ((ks + 1) * XDIM) / 3;
            } else {                       // proj tasks: 8 col-blocks x 2
                is_gate = false;
                int tp = t - 120;
                cb = tp & 7;
                ks = tp >> 3;
                k0x = (ks * XDIM) / 2;
                k1x = ((ks + 1) * XDIM) / 2;
            }

            // ---- stage x slice [k0x,k1x) for 32 nodes, 4-node unroll ----
            for (int mq = 0; mq < CH; mq += 4) {
                int s0 = base + mq;     if (s0 > hi - 1) s0 = hi - 1;
                int s1 = base + mq + 1; if (s1 > hi - 1) s1 = hi - 1;
                int s2 = base + mq + 2; if (s2 > hi - 1) s2 = hi - 1;
                int s3 = base + mq + 3; if (s3 > hi - 1) s3 = hi - 1;
                int n0 = g_order[s0], n1 = g_order[s1];
                int n2 = g_order[s2], n3 = g_order[s3];
                for (int k = k0x + tid; k < k1x; k += NT) {
                    float v0, v1, v2, v3;
                    if (k < INDIM) {
                        v0 = features[(size_t)n0 * INDIM + k];
                        v1 = features[(size_t)n1 * INDIM + k];
                        v2 = features[(size_t)n2 * INDIM + k];
                        v3 = features[(size_t)n3 * INDIM + k];
                    } else {
                        int d = k - INDIM;
                        v0 = g_pe[(size_t)n0 * EMB + d];
                        v1 = g_pe[(size_t)n1 * EMB + d];
                        v2 = g_pe[(size_t)n2 * EMB + d];
                        v3 = g_pe[(size_t)n3 * EMB + d];
                    }
                    float* row = xs + (size_t)(k - k0x) * NSTR + mq;
                    row[0] = v0; row[1] = v1; row[2] = v2; row[3] = v3;
                }
            }
            __syncthreads();

            const int colt = tid & 31;
            const int wid  = tid >> 5;
            const int ng   = wid & 1;          // node group: nodes ng*16..+16
            const int kq   = wid >> 1;         // intra-CTA k eighth (0..7)
            float2 acc[8][4];
#pragma unroll
            for (int p = 0; p < 8; ++p)
#pragma unroll
                for (int c = 0; c < 4; ++c) acc[p][c] = make_float2(0.f, 0.f);

            const float* Wb;
            int stride;
            if (is_gate) { stride = GC;  Wb = W_iofux + cb * 128 + colt * 4; }
            else         { stride = HID; Wb = W_px + cb * 128 + colt * 4; }

            {   // x pass
                int len = k1x - k0x;
                int ka = k0x + (len * kq) / 8;
                int kb = k0x + (len * (kq + 1)) / 8;
                pass_accum2(Wb, stride, xs + ng * 16, k0x, ka, kb, acc);
            }

            if (is_gate) {
                const int p0 = (ks * HID) / 3;
                const int p1 = ((ks + 1) * HID) / 3;
                __syncthreads();
                // ---- stage ph slice (0 for roots), 4-node unroll ----
                for (int mq = 0; mq < CH; mq += 4) {
                    int s0 = base + mq;     if (s0 > hi - 1) s0 = hi - 1;
                    int s1 = base + mq + 1; if (s1 > hi - 1) s1 = hi - 1;
                    int s2 = base + mq + 2; if (s2 > hi - 1) s2 = hi - 1;
                    int s3 = base + mq + 3; if (s3 > hi - 1) s3 = hi - 1;
                    int pa = parent[g_order[s0]], pb = parent[g_order[s1]];
                    int pc = parent[g_order[s2]], pd = parent[g_order[s3]];
                    for (int k = p0 + tid; k < p1; k += NT) {
                        float v0 = (pa >= 0) ? g_h[(size_t)pa * HID + k] : 0.0f;
                        float v1 = (pb >= 0) ? g_h[(size_t)pb * HID + k] : 0.0f;
                        float v2 = (pc >= 0) ? g_h[(size_t)pc * HID + k] : 0.0f;
                        float v3 = (pd >= 0) ? g_h[(size_t)pd * HID + k] : 0.0f;
                        float* row = xs + (size_t)(k - p0) * NSTR + mq;
                        row[0] = v0; row[1] = v1; row[2] = v2; row[3] = v3;
                    }
                }
                __syncthreads();
                int len = p1 - p0;
                int ka = p0 + (len * kq) / 8;
                int kb = p0 + (len * (kq + 1)) / 8;
                pass_accum2(W_iofuh + cb * 128 + colt * 4, GC,
                            xs + ng * 16, p0, ka, kb, acc);
            }

            // ---- reduce 8 k-eighths through smem (overlay xs) ----
            __syncthreads();
            float* red = smf;   // [8 eighths][32 nodes][128 cols]
#pragma unroll
            for (int p = 0; p < 8; ++p) {
                float4 lo4 = make_float4(acc[p][0].x, acc[p][1].x, acc[p][2].x, acc[p][3].x);
                float4 hi4 = make_float4(acc[p][0].y, acc[p][1].y, acc[p][2].y, acc[p][3].y);
                int rowA = kq * 32 + ng * 16 + 2 * p;
                *reinterpret_cast<float4*>(red + (size_t)rowA       * 128 + colt * 4) = lo4;
                *reinterpret_cast<float4*>(red + (size_t)(rowA + 1) * 128 + colt * 4) = hi4;
            }
            __syncthreads();

            {   // 512 threads: node = tid>>4, 8 cols each
                const int m  = tid >> 4;
                const int c0 = (tid & 15) * 8;
                int slot = base + m; if (slot > hi - 1) slot = hi - 1;
                int node = g_order[slot];
                int gcol = is_gate ? (cb * 128 + c0) : (GC + cb * 128 + c0);
                float* dst = &g_part[ks][(size_t)node * OC + gcol];
#pragma unroll
                for (int i = 0; i < 2; ++i) {
                    float4 s = make_float4(0.f, 0.f, 0.f, 0.f);
#pragma unroll
                    for (int q = 0; q < 8; ++q) {
                        float4 v = *reinterpret_cast<const float4*>(
                            red + (size_t)(q * 32 + m) * 128 + c0 + i * 4);
                        s.x += v.x; s.y += v.y; s.z += v.z; s.w += v.w;
                    }
                    if (ks == 0) {
                        float4 bb;
                        if (is_gate) {
                            float4 b1 = *reinterpret_cast<const float4*>(b_iofux + gcol + i * 4);
                            float4 b2 = *reinterpret_cast<const float4*>(b_iofuh + gcol + i * 4);
                            bb = make_float4(b1.x + b2.x, b1.y + b2.y, b1.z + b2.z, b1.w + b2.w);
                        } else {
                            bb = *reinterpret_cast<const float4*>(
                                b_px + (gcol - GC) + i * 4);
                        }
                        s.x += bb.x; s.y += bb.y; s.z += bb.z; s.w += bb.w;
                    }
                    *reinterpret_cast<float4*>(dst + i * 4) = s;
                }
            }
            __syncthreads();   // xs/red reuse on next task
        }
        grid_sync();

        // ---------- stage CD: gates + output head, one CTA per node ----------
        for (int s = blockIdx.x; s < W; s += gridDim.x) {
            const int node = g_order[lo + s];
            const int par  = parent[node];
            const float* q0 = g_part[0] + (size_t)node * OC;
            const float* q1 = g_part[1] + (size_t)node * OC;
            const float* q2 = g_part[2] + (size_t)node * OC;
            float* hb   = smf;              // h_final, 1024 floats
            float* part = smf + HID;        // 512 partials for W_out GEMV
            float* db   = smf + HID + 512;  // dist, 151 floats
            int*   cms  = reinterpret_cast<int*>(smf) + HID + 512 + 256;

            const int j = tid * 2;          // 512*2 == 1024
#define GSUM3(OFF) make_float2( \
            q0[(OFF) + j] + q1[(OFF) + j] + q2[(OFF) + j], \
            q0[(OFF) + j + 1] + q1[(OFF) + j + 1] + q2[(OFF) + j + 1])
            float2 ig2 = GSUM3(0);
            float2 og2 = GSUM3(HID);
            float2 fg2 = GSUM3(2 * HID);
            float2 ug2 = GSUM3(3 * HID);
            float2 rg2 = GSUM3(4 * HID);
#undef GSUM3
            float2 pj2 = make_float2(                     // proj: 2-way split
                q0[5 * HID + j]     + q1[5 * HID + j],
                q0[5 * HID + j + 1] + q1[5 * HID + j + 1]);
            float2 pc2 = make_float2(0.f, 0.f);
            if (par >= 0)
                pc2 = *reinterpret_cast<const float2*>(g_c + (size_t)par * HID + j);

            float2 c2, hf2;
            {
                float iS, oS, fS, rS, cv, hv;
#define ELT(CC, HH, IG, OG, FG, UG, RG, PJ, PC)            \
                iS = sigf(IG); oS = sigf(OG); fS = sigf(FG); rS = sigf(RG); \
                cv = iS * tanhf(UG) + fS * (PC);           \
                hv = oS * tanhf(cv);                       \
                CC = cv; HH = rS * hv + (1.0f - rS) * (PJ);
                ELT(c2.x, hf2.x, ig2.x, og2.x, fg2.x, ug2.x, rg2.x, pj2.x, pc2.x)
                ELT(c2.y, hf2.y, ig2.y, og2.y, fg2.y, ug2.y, rg2.y, pj2.y, pc2.y)
#undef ELT
            }
            *reinterpret_cast<float2*>(g_c + (size_t)node * HID + j) = c2;
            *reinterpret_cast<float2*>(g_h + (size_t)node * HID + j) = hf2;
            *reinterpret_cast<float2*>(hb + j) = hf2;
            __syncthreads();

            // dist = h_final @ W_out + b_out ; 2-way k-split, 4 accumulators
            {
                const int c   = tid & 255;
                const int seg = tid >> 8;
                if (c < NCLS) {
                    const float* wc = W_out + c;
                    const int k0 = seg * 512;
                    float a0 = (seg == 0) ? b_out[c] : 0.0f;
                    float a1 = 0.f, a2 = 0.f, a3 = 0.f;
#pragma unroll 4
                    for (int k = k0; k < k0 + 512; k += 4) {
                        a0 = fmaf(hb[k],     wc[(size_t)(k)     * NCLS], a0);
                        a1 = fmaf(hb[k + 1], wc[(size_t)(k + 1) * NCLS], a1);
                        a2 = fmaf(hb[k + 2], wc[(size_t)(k + 2) * NCLS], a2);
                        a3 = fmaf(hb[k + 3], wc[(size_t)(k + 3) * NCLS], a3);
                    }
                    part[seg * 256 + c] = (a0 + a1) + (a2 + a3);
                }
            }
            __syncthreads();
            if (tid < NCLS) {
                float a = part[tid] + part[256 + tid];
                db[tid] = a;
                if (node >= B) {
                    size_t off = (size_t)(node - B) * NCLS + tid;
                    if (off < (size_t)out_size) out[off] = a;
                }
            }
            __syncthreads();

            // warp-parallel argmax over dist[1:], first-max semantics
            if (tid < 32) {
                float best = -3.4e38f; int bi = NCLS;
                for (int q = 1 + tid; q < NCLS; q += 32) {
                    float v = db[q];
                    if (v > best) { best = v; bi = q; }
                }
#pragma unroll
                for (int off = 16; off > 0; off >>= 1) {
                    float ov = __shfl_down_sync(0xffffffffu, best, off);
                    int   oi = __shfl_down_sync(0xffffffffu, bi, off);
                    if (ov > best || (ov == best && oi < bi)) { best = ov; bi = oi; }
                }
                if (tid == 0) { g_commit[node] = bi; cms[0] = bi; }
            }
            __syncthreads();

            // scatter embed[commit] into children's pe slots
            const int cm = cms[0];
            const int cs = g_choff[node];
            const int ce = g_choff[node + 1];
            const int tot = (ce - cs) * EMB;
            const float* erow = embed + (size_t)cm * EMB;
            for (int e = tid; e < tot; e += NT) {
                int q = e / EMB;
                int d = e - q * EMB;
                int ch = g_chlist[cs + q];
                g_pe[(size_t)ch * EMB + d] = erow[d];
            }
            __syncthreads();
        }
        grid_sync();
    }

    // ================= commitments tail =================
    const int NBo = n - B;
    for (int jj = blockIdx.x * NT + tid; jj < n; jj += gridDim.x * NT) {
        size_t off = (size_t)NBo * NCLS + jj;
        if (off < (size_t)out_size) {
            float v = (jj < NBo) ? (float)g_commit[B + jj] : 0.0f;
            out[off] = v;
        }
    }
}

// ----- host launcher ----------------------------------------------------------
extern "C" void kernel_launch(void* const* d_in, const int* in_sizes, int n_in,
                              void* d_out, int out_size)
{
    const float* features = (const float*)d_in[0];
    const int*   parent   = (const int*)  d_in[1];

    const int* bptr = nullptr;
    int base = 2;
    if (n_in >= 12) { bptr = (const int*)d_in[2]; base = 3; }

    const float* W_px    = (const float*)d_in[base + 0];
    const float* b_px    = (const float*)d_in[base + 1];
    const float* W_iofux = (const float*)d_in[base + 2];
    const float* b_iofux = (const float*)d_in[base + 3];
    const float* W_iofuh = (const float*)d_in[base + 4];
    const float* b_iofuh = (const float*)d_in[base + 5];
    const float* W_out   = (const float*)d_in[base + 6];
    const float* b_out   = (const float*)d_in[base + 7];
    const float* embed   = (const float*)d_in[base + 8];

    int n = in_sizes[1];
    if (n > NMAX) n = NMAX;

    int dev = 0, sms = 0;
    cudaGetDevice(&dev);
    cudaDeviceGetAttribute(&sms, cudaDevAttrMultiProcessorCount, dev);
    if (sms <= 0) sms = 148;

    cudaFuncSetAttribute(tree_lstm_kernel,
                         cudaFuncAttributeMaxDynamicSharedMemorySize, SMEMB);

    tree_lstm_kernel<<<sms, NT, SMEMB>>>(
        features, parent, bptr,
        W_px, b_px, W_iofux, b_iofux, W_iofuh, b_iofuh,
        W_out, b_out, embed,
        (float*)d_out, n, (long long)out_size);
}

// round 11
// speedup vs baseline: 3.0665x; 1.3166x over previous
#include <cuda_runtime.h>
#include <cstdint>
#include <cstddef>

// ---------------------------------------------------------------------------
// DecoderTreeLSTM — round 10: hoist tree-independent GEMM out of the level loop
//   Phase A (once, no barriers):
//     g_base[n][6144] = features @ [W_iofux | W_px](rows 0..2048) + biases
//     E[152][6144]    = embed_table @ [W_iofux | W_px](rows 2048..2248)
//   Per level: ONLY ph @ W_iofuh (gates). proj + pe become lookups in CD.
//   Work-stealing task counters (reset each launch in prep).
// ---------------------------------------------------------------------------

#define NT      512
#define NMAX    1024
#define INDIM   2048
#define EMB     200
#define XDIM    2248
#define HID     1024
#define GC      5120          // 5*HID gate columns
#define OC      6144          // GC + HID
#define NCLS    151
#define NEMB    152           // NUM_CLASSES + 1
#define CH      32            // nodes per chunk
#define NSTR    34            // smem row stride (floats): 2-way store conflicts, 8B aligned
#define SMEMB   (131072 + 16) // red buffer [8][32][128] floats + task slot

// ----- device scratch (static; no allocations anywhere) --------------------
__device__ float g_h[NMAX * HID];
__device__ float g_c[NMAX * HID];
__device__ float g_base[NMAX * OC];       // features @ W + biases
__device__ float g_E[NEMB * OC];          // embed @ W rows [2048:2248)
__device__ float g_part[3][NMAX * GC];    // per-level ph@W_iofuh partials
__device__ int   g_commit[NMAX];
__device__ int   g_order[NMAX];
__device__ int   g_lvloff[NMAX + 1];
__device__ int   g_nlev;
__device__ int   g_taskA;
__device__ int   g_taskL[NMAX];
__device__ volatile unsigned g_gen;
__device__ unsigned g_cnt;

// ----- helpers --------------------------------------------------------------
__device__ __forceinline__ float sigf(float x) {
    return 1.0f / (1.0f + expf(-x));
}

__device__ __forceinline__ float2 ffma2(float2 a, float2 b, float2 c) {
    unsigned long long ua = reinterpret_cast<unsigned long long&>(a);
    unsigned long long ub = reinterpret_cast<unsigned long long&>(b);
    unsigned long long uc = reinterpret_cast<unsigned long long&>(c);
    unsigned long long ud;
    asm("fma.rn.f32x2 %0, %1, %2, %3;" : "=l"(ud) : "l"(ua), "l"(ub), "l"(uc));
    return reinterpret_cast<float2&>(ud);
}

// Sense-reversing grid barrier. Safe: grid == #SMs, 1 CTA/SM (regs+smem).
__device__ __forceinline__ void grid_sync() {
    __threadfence();
    __syncthreads();
    if (threadIdx.x == 0) {
        unsigned gen = g_gen;
        unsigned a = atomicAdd(&g_cnt, 1u);
        if (a == gridDim.x - 1u) {
            g_cnt = 0u;
            __threadfence();
            g_gen = gen + 1u;
        } else {
            while (g_gen == gen) { __nanosleep(64); }
        }
    }
    __syncthreads();
}

// One k-step: 8x LDS.64 broadcast of x (16 nodes), 32 FFMA2 into 8x4 accs.
__device__ __forceinline__ void stepk(const float4 w, const float* __restrict__ xrow,
                                      float2 acc[8][4])
{
    float2 wd0 = make_float2(w.x, w.x);
    float2 wd1 = make_float2(w.y, w.y);
    float2 wd2 = make_float2(w.z, w.z);
    float2 wd3 = make_float2(w.w, w.w);
    const float2* xr = reinterpret_cast<const float2*>(xrow);
    float2 xp[8];
#pragma unroll
    for (int p = 0; p < 8; ++p) xp[p] = xr[p];
#pragma unroll
    for (int p = 0; p < 8; ++p) {
        acc[p][0] = ffma2(xp[p], wd0, acc[p][0]);
        acc[p][1] = ffma2(xp[p], wd1, acc[p][1]);
        acc[p][2] = ffma2(xp[p], wd2, acc[p][2]);
        acc[p][3] = ffma2(xp[p], wd3, acc[p][3]);
    }
}

// Pipelined rank-1 update over absolute W rows [ka, kb); x rows relative to
// staged slice start krel0; xbase pre-offset by node group.
__device__ __forceinline__ void pass_accum2(
    const float* __restrict__ Wb, int stride,
    const float* __restrict__ xbase, int krel0,
    int ka, int kb,
    float2 acc[8][4])
{
    const int nk = kb - ka;
    const float* wl = Wb + (size_t)ka * stride;
    const float* xc = xbase + (size_t)(ka - krel0) * NSTR;
    const int kq = nk & ~3;

    if (kq) {
        float4 w0 = *reinterpret_cast<const float4*>(wl);
        float4 w1 = *reinterpret_cast<const float4*>(wl + stride);
        float4 w2 = *reinterpret_cast<const float4*>(wl + 2 * stride);
        float4 w3 = *reinterpret_cast<const float4*>(wl + 3 * stride);
        wl += (size_t)4 * stride;
        for (int b = 4; b < kq; b += 4) {
            stepk(w0, xc, acc); w0 = *reinterpret_cast<const float4*>(wl);              xc += NSTR;
            stepk(w1, xc, acc); w1 = *reinterpret_cast<const float4*>(wl + stride);     xc += NSTR;
            stepk(w2, xc, acc); w2 = *reinterpret_cast<const float4*>(wl + 2 * stride); xc += NSTR;
            stepk(w3, xc, acc); w3 = *reinterpret_cast<const float4*>(wl + 3 * stride); xc += NSTR;
            wl += (size_t)4 * stride;
        }
        stepk(w0, xc, acc); xc += NSTR;
        stepk(w1, xc, acc); xc += NSTR;
        stepk(w2, xc, acc); xc += NSTR;
        stepk(w3, xc, acc); xc += NSTR;
    }
    for (int r = kq; r < nk; ++r) {
        float4 w = *reinterpret_cast<const float4*>(wl);
        wl += stride;
        stepk(w, xc, acc);
        xc += NSTR;
    }
}

// ----- the persistent kernel -------------------------------------------------
__global__ void __launch_bounds__(NT, 1)
tree_lstm_kernel(const float* __restrict__ features,
                 const int*   __restrict__ parent,
                 const int*   __restrict__ bsz_ptr,
                 const float* __restrict__ W_px,   const float* __restrict__ b_px,
                 const float* __restrict__ W_iofux,const float* __restrict__ b_iofux,
                 const float* __restrict__ W_iofuh,const float* __restrict__ b_iofuh,
                 const float* __restrict__ W_out,  const float* __restrict__ b_out,
                 const float* __restrict__ embed,
                 float* __restrict__ out,
                 int n, long long out_size)
{
    extern __shared__ float smf[];
    int* sT = reinterpret_cast<int*>(smf) + 32768;   // task slot after red area
    const int tid = threadIdx.x;
    const int B = bsz_ptr ? bsz_ptr[0] : 8;

    // ================= PREP (CTA 0) =================
    if (blockIdx.x == 0) {
        int* si  = reinterpret_cast<int*>(smf);
        int* anc = si;
        int* lv  = si + 1024;
        int* cnt = si + 2048;
        int* cur = si + 3072;

        // reset work-steal counters (every launch)
        if (tid == 0) g_taskA = 0;
        for (int i = tid; i < NMAX; i += NT) g_taskL[i] = 0;

        for (int i = tid; i < n; i += NT) {
            int p = parent[i];
            anc[i] = p;
            lv[i]  = (p >= 0) ? 1 : 0;
        }
        __syncthreads();

        for (int it = 0; it < 10; ++it) {     // pointer-doubling depth
            int ra[2], rl[2];
            int q = 0;
            for (int i = tid; i < n; i += NT, ++q) {
                int a = anc[i];
                rl[q] = (a >= 0) ? lv[a]  : 0;
                ra[q] = (a >= 0) ? anc[a] : -1;
            }
            __syncthreads();
            q = 0;
            for (int i = tid; i < n; i += NT, ++q) {
                lv[i]  += rl[q];
                anc[i]  = ra[q];
            }
            __syncthreads();
        }

        for (int i = tid; i < n; i += NT) cnt[i] = 0;
        if (tid == 0) si[4096] = 0;
        __syncthreads();
        int mx = 0;
        for (int i = tid; i < n; i += NT) {
            atomicAdd(&cnt[lv[i]], 1);
            if (lv[i] > mx) mx = lv[i];
        }
        atomicMax(&si[4096], mx);
        __syncthreads();
        int nlev = si[4096] + 1;

        if (tid == 0) {
            int s0 = 0;
            for (int l = 0; l < nlev; ++l) { g_lvloff[l] = s0; cur[l] = s0; s0 += cnt[l]; }
            g_lvloff[nlev] = s0;
            g_nlev = nlev;
        }
        __syncthreads();
        for (int i = tid; i < n; i += NT) {
            int pos = atomicAdd(&cur[lv[i]], 1);
            g_order[pos] = i;
        }
    }
    grid_sync();

    const int colt = tid & 31;
    const int wid  = tid >> 5;
    const int ng   = wid & 1;          // node group (16 nodes)
    const int kq8  = wid >> 1;         // k-eighth (0..7)

    // ================= PHASE A (work-stealing, no barriers) =================
    {
        const int chunksA = (n + CH - 1) / CH;
        const int ntF = chunksA * 48;        // feature GEMM tasks
        const int ntA = ntF + 5 * 48;        // + embed-table tasks (152 -> 5 chunks)

        for (;;) {
            if (tid == 0) sT[0] = atomicAdd(&g_taskA, 1);
            __syncthreads();
            const int task = sT[0];
            if (task >= ntA) break;

            float* xs = smf;
            float2 acc[8][4];
#pragma unroll
            for (int p = 0; p < 8; ++p)
#pragma unroll
                for (int c = 0; c < 4; ++c) acc[p][c] = make_float2(0.f, 0.f);

            if (task < ntF) {
                // -------- features GEMM task: K=2048 in 4 slabs of 512 --------
                const int chunk = task / 48;
                const int cb    = task % 48;
                const int base  = chunk * CH;

                const float* Wb;
                int stride;
                if (cb < 40) { stride = GC;  Wb = W_iofux + cb * 128 + colt * 4; }
                else         { stride = HID; Wb = W_px + (cb - 40) * 128 + colt * 4; }

                for (int slab = 0; slab < 4; ++slab) {
                    const int s0 = slab * 512;
                    const int k  = s0 + tid;        // 512 threads = 512 rows
#pragma unroll 1
                    for (int mq = 0; mq < CH; mq += 4) {
                        int m0 = base + mq;     if (m0 > n - 1) m0 = n - 1;
                        int m1 = base + mq + 1; if (m1 > n - 1) m1 = n - 1;
                        int m2 = base + mq + 2; if (m2 > n - 1) m2 = n - 1;
                        int m3 = base + mq + 3; if (m3 > n - 1) m3 = n - 1;
                        float v0 = features[(size_t)m0 * INDIM + k];
                        float v1 = features[(size_t)m1 * INDIM + k];
                        float v2 = features[(size_t)m2 * INDIM + k];
                        float v3 = features[(size_t)m3 * INDIM + k];
                        float* row = xs + (size_t)tid * NSTR + mq;
                        *reinterpret_cast<float2*>(row)     = make_float2(v0, v1);
                        *reinterpret_cast<float2*>(row + 2) = make_float2(v2, v3);
                    }
                    __syncthreads();
                    int ka = s0 + kq8 * 64;
                    pass_accum2(Wb, stride, xs + ng * 16, s0, ka, ka + 64, acc);
                    __syncthreads();
                }

                // reduce [8][32][128]
                float* red = smf;
#pragma unroll
                for (int p = 0; p < 8; ++p) {
                    float4 lo4 = make_float4(acc[p][0].x, acc[p][1].x, acc[p][2].x, acc[p][3].x);
                    float4 hi4 = make_float4(acc[p][0].y, acc[p][1].y, acc[p][2].y, acc[p][3].y);
                    int rowA = kq8 * 32 + ng * 16 + 2 * p;
                    *reinterpret_cast<float4*>(red + (size_t)rowA       * 128 + colt * 4) = lo4;
                    *reinterpret_cast<float4*>(red + (size_t)(rowA + 1) * 128 + colt * 4) = hi4;
                }
                __syncthreads();
                {
                    const int m  = tid >> 4;
                    const int c0 = (tid & 15) * 8;
                    int node = base + m; if (node > n - 1) node = n - 1;
                    int gcol = (cb < 40) ? (cb * 128 + c0) : (GC + (cb - 40) * 128 + c0);
                    float* dst = g_base + (size_t)node * OC + gcol;
#pragma unroll
                    for (int i = 0; i < 2; ++i) {
                        float4 s = make_float4(0.f, 0.f, 0.f, 0.f);
#pragma unroll
                        for (int q = 0; q < 8; ++q) {
                            float4 v = *reinterpret_cast<const float4*>(
                                red + (size_t)(q * 32 + m) * 128 + c0 + i * 4);
                            s.x += v.x; s.y += v.y; s.z += v.z; s.w += v.w;
                        }
                        float4 bb;
                        if (cb < 40) {
                            float4 b1 = *reinterpret_cast<const float4*>(b_iofux + gcol + i * 4);
                            float4 b2 = *reinterpret_cast<const float4*>(b_iofuh + gcol + i * 4);
                            bb = make_float4(b1.x + b2.x, b1.y + b2.y, b1.z + b2.z, b1.w + b2.w);
                        } else {
                            bb = *reinterpret_cast<const float4*>(b_px + (gcol - GC) + i * 4);
                        }
                        s.x += bb.x; s.y += bb.y; s.z += bb.z; s.w += bb.w;
                        *reinterpret_cast<float4*>(dst + i * 4) = s;
                    }
                }
            } else {
                // -------- embed-table GEMM task: 32 pseudo-nodes, K=200 --------
                const int et    = task - ntF;
                const int chunk = et / 48;
                const int cb    = et % 48;
                const int base  = chunk * CH;

#pragma unroll 1
                for (int mq = 0; mq < CH; mq += 4) {
                    int e0 = base + mq;     if (e0 > NEMB - 1) e0 = NEMB - 1;
                    int e1 = base + mq + 1; if (e1 > NEMB - 1) e1 = NEMB - 1;
                    int e2 = base + mq + 2; if (e2 > NEMB - 1) e2 = NEMB - 1;
                    int e3 = base + mq + 3; if (e3 > NEMB - 1) e3 = NEMB - 1;
                    for (int k = tid; k < EMB; k += NT) {
                        float v0 = embed[(size_t)e0 * EMB + k];
                        float v1 = embed[(size_t)e1 * EMB + k];
                        float v2 = embed[(size_t)e2 * EMB + k];
                        float v3 = embed[(size_t)e3 * EMB + k];
                        float* row = xs + (size_t)k * NSTR + mq;
                        *reinterpret_cast<float2*>(row)     = make_float2(v0, v1);
                        *reinterpret_cast<float2*>(row + 2) = make_float2(v2, v3);
                    }
                }
                __syncthreads();

                const float* Wb;
                int stride;
                if (cb < 40) { stride = GC;  Wb = W_iofux + (size_t)INDIM * GC + cb * 128 + colt * 4; }
                else         { stride = HID; Wb = W_px + (size_t)INDIM * HID + (cb - 40) * 128 + colt * 4; }

                int ka = (EMB * kq8) / 8;
                int kb = (EMB * (kq8 + 1)) / 8;
                pass_accum2(Wb, stride, xs + ng * 16, 0, ka, kb, acc);
                __syncthreads();

                float* red = smf;
#pragma unroll
                for (int p = 0; p < 8; ++p) {
                    float4 lo4 = make_float4(acc[p][0].x, acc[p][1].x, acc[p][2].x, acc[p][3].x);
                    float4 hi4 = make_float4(acc[p][0].y, acc[p][1].y, acc[p][2].y, acc[p][3].y);
                    int rowA = kq8 * 32 + ng * 16 + 2 * p;
                    *reinterpret_cast<float4*>(red + (size_t)rowA       * 128 + colt * 4) = lo4;
                    *reinterpret_cast<float4*>(red + (size_t)(rowA + 1) * 128 + colt * 4) = hi4;
                }
                __syncthreads();
                {
                    const int m  = tid >> 4;
                    const int c0 = (tid & 15) * 8;
                    int e = base + m; if (e > NEMB - 1) e = NEMB - 1;
                    int gcol = (cb < 40) ? (cb * 128 + c0) : (GC + (cb - 40) * 128 + c0);
                    float* dst = g_E + (size_t)e * OC + gcol;
#pragma unroll
                    for (int i = 0; i < 2; ++i) {
                        float4 s = make_float4(0.f, 0.f, 0.f, 0.f);
#pragma unroll
                        for (int q = 0; q < 8; ++q) {
                            float4 v = *reinterpret_cast<const float4*>(
                                red + (size_t)(q * 32 + m) * 128 + c0 + i * 4);
                            s.x += v.x; s.y += v.y; s.z += v.z; s.w += v.w;
                        }
                        *reinterpret_cast<float4*>(dst + i * 4) = s;
                    }
                }
            }
        }
    }
    grid_sync();

    const int nlev = g_nlev;

    // ================= LEVEL LOOP =================
    for (int lev = 0; lev < nlev; ++lev) {
        const int lo = g_lvloff[lev];
        const int hi = g_lvloff[lev + 1];
        const int W  = hi - lo;

        // ---------- stage B: ph @ W_iofuh only (work-stealing) ----------
        const int chunks = (W + CH - 1) / CH;
        const int ntL = chunks * 120;           // 40 col-blocks x 3 k-splits
        for (;;) {
            if (tid == 0) sT[0] = atomicAdd(&g_taskL[lev], 1);
            __syncthreads();
            const int task = sT[0];
            if (task >= ntL) break;

            const int t     = task % 120;
            const int chunk = task / 120;
            const int cb    = t % 40;
            const int ks    = t / 40;
            const int base  = lo + chunk * CH;
            const int r0 = (ks * HID) / 3;
            const int r1 = ((ks + 1) * HID) / 3;
            float* xs = smf;

            // stage ph rows [r0,r1) for 32 nodes (0 for roots)
#pragma unroll 1
            for (int mq = 0; mq < CH; mq += 4) {
                int s0 = base + mq;     if (s0 > hi - 1) s0 = hi - 1;
                int s1 = base + mq + 1; if (s1 > hi - 1) s1 = hi - 1;
                int s2 = base + mq + 2; if (s2 > hi - 1) s2 = hi - 1;
                int s3 = base + mq + 3; if (s3 > hi - 1) s3 = hi - 1;
                int pa = parent[g_order[s0]], pb = parent[g_order[s1]];
                int pc = parent[g_order[s2]], pd = parent[g_order[s3]];
                for (int k = r0 + tid; k < r1; k += NT) {
                    float v0 = (pa >= 0) ? g_h[(size_t)pa * HID + k] : 0.0f;
                    float v1 = (pb >= 0) ? g_h[(size_t)pb * HID + k] : 0.0f;
                    float v2 = (pc >= 0) ? g_h[(size_t)pc * HID + k] : 0.0f;
                    float v3 = (pd >= 0) ? g_h[(size_t)pd * HID + k] : 0.0f;
                    float* row = xs + (size_t)(k - r0) * NSTR + mq;
                    *reinterpret_cast<float2*>(row)     = make_float2(v0, v1);
                    *reinterpret_cast<float2*>(row + 2) = make_float2(v2, v3);
                }
            }
            __syncthreads();

            float2 acc[8][4];
#pragma unroll
            for (int p = 0; p < 8; ++p)
#pragma unroll
                for (int c = 0; c < 4; ++c) acc[p][c] = make_float2(0.f, 0.f);

            const int len = r1 - r0;
            const int ka = r0 + (len * kq8) / 8;
            const int kb = r0 + (len * (kq8 + 1)) / 8;
            pass_accum2(W_iofuh + cb * 128 + colt * 4, GC, xs + ng * 16, r0, ka, kb, acc);

            __syncthreads();
            float* red = smf;
#pragma unroll
            for (int p = 0; p < 8; ++p) {
                float4 lo4 = make_float4(acc[p][0].x, acc[p][1].x, acc[p][2].x, acc[p][3].x);
                float4 hi4 = make_float4(acc[p][0].y, acc[p][1].y, acc[p][2].y, acc[p][3].y);
                int rowA = kq8 * 32 + ng * 16 + 2 * p;
                *reinterpret_cast<float4*>(red + (size_t)rowA       * 128 + colt * 4) = lo4;
                *reinterpret_cast<float4*>(red + (size_t)(rowA + 1) * 128 + colt * 4) = hi4;
            }
            __syncthreads();
            {
                const int m  = tid >> 4;
                const int c0 = (tid & 15) * 8;
                int slot = base + m; if (slot > hi - 1) slot = hi - 1;
                int node = g_order[slot];
                int gcol = cb * 128 + c0;
                float* dst = g_part[ks] + (size_t)node * GC + gcol;
#pragma unroll
                for (int i = 0; i < 2; ++i) {
                    float4 s = make_float4(0.f, 0.f, 0.f, 0.f);
#pragma unroll
                    for (int q = 0; q < 8; ++q) {
                        float4 v = *reinterpret_cast<const float4*>(
                            red + (size_t)(q * 32 + m) * 128 + c0 + i * 4);
                        s.x += v.x; s.y += v.y; s.z += v.z; s.w += v.w;
                    }
                    *reinterpret_cast<float4*>(dst + i * 4) = s;
                }
            }
        }
        grid_sync();

        // ---------- stage CD: gates + output head, one CTA per node ----------
        for (int s = blockIdx.x; s < W; s += gridDim.x) {
            const int node = g_order[lo + s];
            const int par  = parent[node];
            const int cmIdx = (par >= 0) ? g_commit[par] : 0;
            const float* gb = g_base + (size_t)node * OC;
            const float* er = g_E + (size_t)cmIdx * OC;
            const float* p0 = g_part[0] + (size_t)node * GC;
            const float* p1 = g_part[1] + (size_t)node * GC;
            const float* p2 = g_part[2] + (size_t)node * GC;
            float* hb   = smf;              // h_final, 1024 floats
            float* part = smf + HID;        // 512 partials for W_out GEMV
            float* db   = smf + HID + 512;  // dist, 151 floats
            int*   cms  = reinterpret_cast<int*>(smf) + HID + 512 + 256;

            const int j = tid * 2;          // 512*2 == 1024
#define GGATE(OFF) make_float2( \
            gb[(OFF) + j]     + er[(OFF) + j]     + p0[(OFF) + j]     + p1[(OFF) + j]     + p2[(OFF) + j], \
            gb[(OFF) + j + 1] + er[(OFF) + j + 1] + p0[(OFF) + j + 1] + p1[(OFF) + j + 1] + p2[(OFF) + j + 1])
            float2 ig2 = GGATE(0);
            float2 og2 = GGATE(HID);
            float2 fg2 = GGATE(2 * HID);
            float2 ug2 = GGATE(3 * HID);
            float2 rg2 = GGATE(4 * HID);
#undef GGATE
            float2 pj2 = make_float2(gb[GC + j]     + er[GC + j],
                                     gb[GC + j + 1] + er[GC + j + 1]);
            float2 pc2 = make_float2(0.f, 0.f);
            if (par >= 0)
                pc2 = *reinterpret_cast<const float2*>(g_c + (size_t)par * HID + j);

            float2 c2, hf2;
            {
                float iS, oS, fS, rS, cv, hv;
#define ELT(CC, HH, IG, OG, FG, UG, RG, PJ, PC)            \
                iS = sigf(IG); oS = sigf(OG); fS = sigf(FG); rS = sigf(RG); \
                cv = iS * tanhf(UG) + fS * (PC);           \
                hv = oS * tanhf(cv);                       \
                CC = cv; HH = rS * hv + (1.0f - rS) * (PJ);
                ELT(c2.x, hf2.x, ig2.x, og2.x, fg2.x, ug2.x, rg2.x, pj2.x, pc2.x)
                ELT(c2.y, hf2.y, ig2.y, og2.y, fg2.y, ug2.y, rg2.y, pj2.y, pc2.y)
#undef ELT
            }
            *reinterpret_cast<float2*>(g_c + (size_t)node * HID + j) = c2;
            *reinterpret_cast<float2*>(g_h + (size_t)node * HID + j) = hf2;
            *reinterpret_cast<float2*>(hb + j) = hf2;
            __syncthreads();

            // dist = h_final @ W_out + b_out ; 2-way k-split, 4 accumulators
            {
                const int c   = tid & 255;
                const int seg = tid >> 8;
                if (c < NCLS) {
                    const float* wc = W_out + c;
                    const int k0 = seg * 512;
                    float a0 = (seg == 0) ? b_out[c] : 0.0f;
                    float a1 = 0.f, a2 = 0.f, a3 = 0.f;
#pragma unroll 4
                    for (int k = k0; k < k0 + 512; k += 4) {
                        a0 = fmaf(hb[k],     wc[(size_t)(k)     * NCLS], a0);
                        a1 = fmaf(hb[k + 1], wc[(size_t)(k + 1) * NCLS], a1);
                        a2 = fmaf(hb[k + 2], wc[(size_t)(k + 2) * NCLS], a2);
                        a3 = fmaf(hb[k + 3], wc[(size_t)(k + 3) * NCLS], a3);
                    }
                    part[seg * 256 + c] = (a0 + a1) + (a2 + a3);
                }
            }
            __syncthreads();
            if (tid < NCLS) {
                float a = part[tid] + part[256 + tid];
                db[tid] = a;
                if (node >= B) {
                    size_t off = (size_t)(node - B) * NCLS + tid;
                    if (off < (size_t)out_size) out[off] = a;
                }
            }
            __syncthreads();

            // warp-parallel argmax over dist[1:], first-max semantics
            if (tid < 32) {
                float best = -3.4e38f; int bi = NCLS;
                for (int q = 1 + tid; q < NCLS; q += 32) {
                    float v = db[q];
                    if (v > best) { best = v; bi = q; }
                }
#pragma unroll
                for (int off = 16; off > 0; off >>= 1) {
                    float ov = __shfl_down_sync(0xffffffffu, best, off);
                    int   oi = __shfl_down_sync(0xffffffffu, bi, off);
                    if (ov > best || (ov == best && oi < bi)) { best = ov; bi = oi; }
                }
                if (tid == 0) { g_commit[node] = bi; cms[0] = bi; }
            }
            __syncthreads();
        }
        grid_sync();
    }

    // ================= commitments tail =================
    const int NBo = n - B;
    for (int jj = blockIdx.x * NT + tid; jj < n; jj += gridDim.x * NT) {
        size_t off = (size_t)NBo * NCLS + jj;
        if (off < (size_t)out_size) {
            float v = (jj < NBo) ? (float)g_commit[B + jj] : 0.0f;
            out[off] = v;
        }
    }
}

// ----- host launcher ----------------------------------------------------------
extern "C" void kernel_launch(void* const* d_in, const int* in_sizes, int n_in,
                              void* d_out, int out_size)
{
    const float* features = (const float*)d_in[0];
    const int*   parent   = (const int*)  d_in[1];

    const int* bptr = nullptr;
    int base = 2;
    if (n_in >= 12) { bptr = (const int*)d_in[2]; base = 3; }

    const float* W_px    = (const float*)d_in[base + 0];
    const float* b_px    = (const float*)d_in[base + 1];
    const float* W_iofux = (const float*)d_in[base + 2];
    const float* b_iofux = (const float*)d_in[base + 3];
    const float* W_iofuh = (const float*)d_in[base + 4];
    const float* b_iofuh = (const float*)d_in[base + 5];
    const float* W_out   = (const float*)d_in[base + 6];
    const float* b_out   = (const float*)d_in[base + 7];
    const float* embed   = (const float*)d_in[base + 8];

    int n = in_sizes[1];
    if (n > NMAX) n = NMAX;

    int dev = 0, sms = 0;
    cudaGetDevice(&dev);
    cudaDeviceGetAttribute(&sms, cudaDevAttrMultiProcessorCount, dev);
    if (sms <= 0) sms = 148;

    cudaFuncSetAttribute(tree_lstm_kernel,
                         cudaFuncAttributeMaxDynamicSharedMemorySize, SMEMB);

    tree_lstm_kernel<<<sms, NT, SMEMB>>>(
        features, parent, bptr,
        W_px, b_px, W_iofux, b_iofux, W_iofuh, b_iofuh,
        W_out, b_out, embed,
        (float*)d_out, n, (long long)out_size);
}